// round 2
// baseline (speedup 1.0000x reference)
#include <cuda_runtime.h>
#include <cstdint>

#define NBLK 148
#define NTHR 256
#define NWARP (NBLK * 8)
#define M_   2048
#define H_   8192
#define TKN  32
#define TKA  3

// ---------------- persistent device state (no allocs allowed) ----------------
__device__ float g_xcf[TKN * M_];
__device__ float g_s0 [TKN * M_];
__device__ float g_s  [M_];
__device__ float g_sp [M_];
__device__ float g_h  [H_];
__device__ float g_vcum[TKA * M_];
__device__ float g_ln1[TKN * TKA * 2];   // (sum, sumsq) for LN1 input at (i,a)
__device__ float g_ln2[TKN * TKA * 2];   // (sum, sumsq) for LN2 input at (i,a)
__device__ unsigned g_ctr;

// ---------------- global barrier (all 148 blocks co-resident) ----------------
__device__ __forceinline__ void gbar(unsigned target) {
    __threadfence();          // make our writes visible (gpu scope) before arrival
    __syncthreads();
    if (threadIdx.x == 0) {
        atomicAdd(&g_ctr, 1u);
        unsigned v;
        do {
            asm volatile("ld.global.acquire.gpu.u32 %0, [%1];"
                         : "=r"(v) : "l"(&g_ctr) : "memory");
        } while (v < target);
    }
    __syncthreads();
}

// warp dot of one weight row (K4 float4 per lane) against SMEM-staged vector
template <int K4>
__device__ __forceinline__ float dot_row(const float4* __restrict__ wr,
                                         const float4* __restrict__ shv, int lane) {
    float acc = 0.f;
    for (int k0 = 0; k0 < K4; k0 += 16) {
#pragma unroll
        for (int kk = 0; kk < 16; kk++) {
            int idx = lane + (k0 + kk) * 32;
            float4 w  = wr[idx];
            float4 xv = shv[idx];
            acc = fmaf(w.x, xv.x, acc);
            acc = fmaf(w.y, xv.y, acc);
            acc = fmaf(w.z, xv.z, acc);
            acc = fmaf(w.w, xv.w, acc);
        }
    }
#pragma unroll
    for (int o = 16; o; o >>= 1) acc += __shfl_down_sync(0xffffffffu, acc, o);
    return acc;
}

// ---------------- prologue kernels ----------------
__global__ void k_init() {
    int t = threadIdx.x;
    if (t == 0) g_ctr = 0u;
    for (int idx = t; idx < TKN * TKA * 2; idx += NTHR) { g_ln1[idx] = 0.f; g_ln2[idx] = 0.f; }
    for (int idx = t; idx < TKA * M_; idx += NTHR) g_vcum[idx] = 0.f;
}

// xcf[i, b*16+a] = mean over 16 consecutive t of x[a,b,i*16+t]
__global__ void k_xcf(const float* __restrict__ x) {
    int idx = blockIdx.x * blockDim.x + threadIdx.x;
    if (idx >= TKN * M_) return;
    int i = idx >> 11, m = idx & 2047;
    int b = m >> 4, ab = m & 15;
    const float* p = x + ab * (128 * 512) + b * 512 + i * 16;
    float s = 0.f;
#pragma unroll
    for (int t = 0; t < 16; t++) s += p[t];
    g_xcf[idx] = s * (1.0f / 16.0f);
}

// s0[i,m] = sum_k xcf[i,k] * weight[m,k] + sinusoidal bias; also LN1 stats for a=0
__global__ void k_s0(const float* __restrict__ weight) {
    int m = blockIdx.x;
    int tid = threadIdx.x, lane = tid & 31, wid = tid >> 5;
    const float* wr = weight + (size_t)m * M_;
    float acc[TKN];
#pragma unroll
    for (int i = 0; i < TKN; i++) acc[i] = 0.f;
    for (int k = tid; k < M_; k += NTHR) {
        float w = __ldg(&wr[k]);
#pragma unroll
        for (int i = 0; i < TKN; i++) acc[i] = fmaf(w, __ldg(&g_xcf[i * M_ + k]), acc[i]);
    }
#pragma unroll
    for (int i = 0; i < TKN; i++) {
        float v = acc[i];
#pragma unroll
        for (int o = 16; o; o >>= 1) v += __shfl_down_sync(0xffffffffu, v, o);
        acc[i] = v;
    }
    __shared__ float red[8][TKN];
    if (lane == 0) {
#pragma unroll
        for (int i = 0; i < TKN; i++) red[wid][i] = acc[i];
    }
    __syncthreads();
    if (tid < TKN) {
        float v = 0.f;
#pragma unroll
        for (int w = 0; w < 8; w++) v += red[w][tid];
        int p = m >> 1;  // pair index: ang = i * 10000^(-p/512)
        float ang = (float)tid * expf(-(float)p * (9.210340371976184f / 512.0f));
        v += (m & 1) ? cosf(ang) : sinf(ang);
        g_s0[tid * M_ + m] = v;
        atomicAdd(&g_ln1[(tid * TKA + 0) * 2 + 0], v);
        atomicAdd(&g_ln1[(tid * TKA + 0) * 2 + 1], v * v);
    }
}

// ---------------- main persistent kernel ----------------
__global__ void __launch_bounds__(NTHR) k_main(
    const float* __restrict__ Wv,   const float* __restrict__ Wo,
    const float* __restrict__ ln1g, const float* __restrict__ ln1b,
    const float* __restrict__ ln2g, const float* __restrict__ ln2b,
    const float* __restrict__ fc1w, const float* __restrict__ fc1b,
    const float* __restrict__ fc2w, const float* __restrict__ fc2b,
    float* __restrict__ out)
{
    __shared__ float sh[H_];      // 32 KB staging (max of 2048/8192 floats)
    __shared__ float red2[2];
    const int tid = threadIdx.x, lane = tid & 31;
    const int gw = blockIdx.x * (NTHR / 32) + (tid >> 5);
    const float4* shv = (const float4*)sh;
    unsigned barph = 0;

    for (int i = 0; i < TKN; i++) {
        for (int a = 0; a < TKA; a++) {
            const float* svec = (a == 0) ? (g_s0 + i * M_) : g_s;

            // ---- phase V: vcum[a] += Wv[a] @ LN1(s)  (q,k dead: softmax(1)=1) ----
            {
                float ssum = __ldcg(&g_ln1[(i * TKA + a) * 2 + 0]);
                float ssq  = __ldcg(&g_ln1[(i * TKA + a) * 2 + 1]);
                float mu = ssum * (1.0f / M_);
                float var = fmaxf(ssq * (1.0f / M_) - mu * mu, 0.f);
                float rstd = rsqrtf(var + 1e-5f);
                for (int m = tid; m < M_; m += NTHR) {
                    float xx = __ldcg(&svec[m]);
                    sh[m] = (xx - mu) * rstd * ln1g[m] + ln1b[m];
                }
                __syncthreads();
                const float* W = Wv + (size_t)a * M_ * M_;
                for (int j = gw; j < M_; j += NWARP) {
                    float acc = dot_row<16>((const float4*)(W + (size_t)j * M_), shv, lane);
                    if (lane == 0) {
                        float old = __ldcg(&g_vcum[a * M_ + j]);
                        __stcg(&g_vcum[a * M_ + j], old + acc);
                    }
                }
            }
            gbar(++barph * NBLK);

            // ---- phase Wo: s' = Wo[a] @ vcum[a] + s ; emit LN2 stats ----
            {
                if (tid < 2) red2[tid] = 0.f;
                for (int m = tid; m < M_; m += NTHR) sh[m] = __ldcg(&g_vcum[a * M_ + m]);
                __syncthreads();
                const float* W = Wo + (size_t)a * M_ * M_;
                float lsum = 0.f, lsq = 0.f;
                for (int j = gw; j < M_; j += NWARP) {
                    float acc = dot_row<16>((const float4*)(W + (size_t)j * M_), shv, lane);
                    if (lane == 0) {
                        acc += __ldcg(&svec[j]);
                        __stcg(&g_sp[j], acc);
                        lsum += acc; lsq += acc * acc;
                    }
                }
                if (lane == 0) { atomicAdd(&red2[0], lsum); atomicAdd(&red2[1], lsq); }
                __syncthreads();
                if (tid == 0) {
                    atomicAdd(&g_ln2[(i * TKA + a) * 2 + 0], red2[0]);
                    atomicAdd(&g_ln2[(i * TKA + a) * 2 + 1], red2[1]);
                }
            }
            gbar(++barph * NBLK);

            // ---- phase fc1: h = gelu(fc1 @ (LN2(s') + s') + b1) ----
            {
                float ssum = __ldcg(&g_ln2[(i * TKA + a) * 2 + 0]);
                float ssq  = __ldcg(&g_ln2[(i * TKA + a) * 2 + 1]);
                float mu = ssum * (1.0f / M_);
                float var = fmaxf(ssq * (1.0f / M_) - mu * mu, 0.f);
                float rstd = rsqrtf(var + 1e-5f);
                for (int m = tid; m < M_; m += NTHR) {
                    float sp = __ldcg(&g_sp[m]);
                    sh[m] = (sp - mu) * rstd * ln2g[m] + ln2b[m] + sp;
                }
                __syncthreads();
                for (int r = gw; r < H_; r += NWARP) {
                    float acc = dot_row<16>((const float4*)(fc1w + (size_t)r * M_), shv, lane);
                    if (lane == 0) {
                        acc += fc1b[r];
                        float g = 0.5f * acc * (1.0f + erff(acc * 0.70710678118654752f));
                        __stcg(&g_h[r], g);
                    }
                }
            }
            gbar(++barph * NBLK);

            // ---- phase fc2: s_next = fc2 @ h + b2 ; (last a) -> out ; else LN1 stats ----
            {
                if (tid < 2) red2[tid] = 0.f;
                for (int m = tid; m < H_; m += NTHR) sh[m] = __ldcg(&g_h[m]);
                __syncthreads();
                float lsum = 0.f, lsq = 0.f;
                for (int r = gw; r < M_; r += NWARP) {
                    float acc = dot_row<64>((const float4*)(fc2w + (size_t)r * H_), shv, lane);
                    if (lane == 0) {
                        acc += fc2b[r];
                        if (a == TKA - 1) {
                            out[i * M_ + r] = acc;
                        } else {
                            __stcg(&g_s[r], acc);
                            lsum += acc; lsq += acc * acc;
                        }
                    }
                }
                if (a < TKA - 1) {
                    if (lane == 0) { atomicAdd(&red2[0], lsum); atomicAdd(&red2[1], lsq); }
                    __syncthreads();
                    if (tid == 0) {
                        atomicAdd(&g_ln1[(i * TKA + a + 1) * 2 + 0], red2[0]);
                        atomicAdd(&g_ln1[(i * TKA + a + 1) * 2 + 1], red2[1]);
                    }
                }
            }
            gbar(++barph * NBLK);
        }
    }
}

// ---------------- launch ----------------
extern "C" void kernel_launch(void* const* d_in, const int* in_sizes, int n_in,
                              void* d_out, int out_size) {
    const float* x      = (const float*)d_in[0];
    const float* weight = (const float*)d_in[1];
    // d_in[2] = Wq, d_in[3] = Wk: dead code (softmax over size-1 axis == 1)
    const float* Wv     = (const float*)d_in[4];
    const float* Wo     = (const float*)d_in[5];
    const float* ln1g   = (const float*)d_in[6];
    const float* ln1b   = (const float*)d_in[7];
    const float* ln2g   = (const float*)d_in[8];
    const float* ln2b   = (const float*)d_in[9];
    const float* fc1w   = (const float*)d_in[10];
    const float* fc1b   = (const float*)d_in[11];
    const float* fc2w   = (const float*)d_in[12];
    const float* fc2b   = (const float*)d_in[13];
    float* out = (float*)d_out;

    k_init<<<1, NTHR>>>();
    k_xcf<<<(TKN * M_ + NTHR - 1) / NTHR, NTHR>>>(x);
    k_s0<<<M_, NTHR>>>(weight);
    k_main<<<NBLK, NTHR>>>(Wv, Wo, ln1g, ln1b, ln2g, ln2b,
                           fc1w, fc1b, fc2w, fc2b, out);
}

// round 4
// speedup vs baseline: 2.0013x; 2.0013x over previous
#include <cuda_runtime.h>
#include <cstdint>

#define NBLK 148
#define NTHR 1024
#define NWB  32                 // warps per block
#define NWARP (NBLK * NWB)      // 4736
#define M_   2048
#define H_   8192
#define TKN  32
#define TKA  3

// ---------------- persistent device state (no allocs allowed) ----------------
__device__ float g_xcf[TKN * M_];
__device__ float g_s0 [TKN * M_];
__device__ float g_s  [M_];
__device__ float g_sp [M_];
__device__ float g_h  [H_];
__device__ float g_vcum[TKA * M_];
__device__ float g_ln1[TKN * TKA * 2];   // (sum, sumsq) for LN1 input at (i,a)
__device__ float g_ln2[TKN * TKA * 2];   // (sum, sumsq) for LN2 input at (i,a)
__device__ unsigned g_ctr;

// ---------------- global barrier (all 148 blocks co-resident) ----------------
// Release: EVERY thread fences its own prior writes (gpu scope) before the
// block-representative arrival. Acquire: spinning load with .acquire.
__device__ __forceinline__ void gbar(unsigned target) {
    __threadfence();
    __syncthreads();
    if (threadIdx.x == 0) {
        atomicAdd(&g_ctr, 1u);
        unsigned v;
        do {
            asm volatile("ld.global.acquire.gpu.u32 %0, [%1];"
                         : "=r"(v) : "l"(&g_ctr) : "memory");
            if (v < target) __nanosleep(128);
        } while (v < target);
    }
    __syncthreads();
}

__device__ __forceinline__ float wredsum(float v) {
#pragma unroll
    for (int o = 16; o; o >>= 1) v += __shfl_down_sync(0xffffffffu, v, o);
    return v;
}

// ---------------- prologue kernels ----------------
__global__ void k_init() {
    int t = threadIdx.x;
    if (t == 0) g_ctr = 0u;
    for (int idx = t; idx < TKN * TKA * 2; idx += 256) { g_ln1[idx] = 0.f; g_ln2[idx] = 0.f; }
    for (int idx = t; idx < TKA * M_; idx += 256) g_vcum[idx] = 0.f;
}

// xcf[i, b*16+a] = mean over 16 consecutive t of x[a,b,i*16+t]
__global__ void k_xcf(const float* __restrict__ x) {
    int idx = blockIdx.x * blockDim.x + threadIdx.x;
    if (idx >= TKN * M_) return;
    int i = idx >> 11, m = idx & 2047;
    int b = m >> 4, ab = m & 15;
    const float* p = x + ab * (128 * 512) + b * 512 + i * 16;
    float s = 0.f;
#pragma unroll
    for (int t = 0; t < 16; t++) s += p[t];
    g_xcf[idx] = s * (1.0f / 16.0f);
}

// s0[i,m] = sum_k xcf[i,k] * weight[m,k] + sinusoidal bias; also LN1 stats for a=0
__global__ void k_s0(const float* __restrict__ weight) {
    int m = blockIdx.x;
    int tid = threadIdx.x, lane = tid & 31, wid = tid >> 5;
    const float* wr = weight + (size_t)m * M_;
    float acc[TKN];
#pragma unroll
    for (int i = 0; i < TKN; i++) acc[i] = 0.f;
    for (int k = tid; k < M_; k += 256) {
        float w = __ldg(&wr[k]);
#pragma unroll
        for (int i = 0; i < TKN; i++) acc[i] = fmaf(w, __ldg(&g_xcf[i * M_ + k]), acc[i]);
    }
#pragma unroll
    for (int i = 0; i < TKN; i++) acc[i] = wredsum(acc[i]);
    __shared__ float red[8][TKN];
    if (lane == 0) {
#pragma unroll
        for (int i = 0; i < TKN; i++) red[wid][i] = acc[i];
    }
    __syncthreads();
    if (tid < TKN) {
        float v = 0.f;
#pragma unroll
        for (int w = 0; w < 8; w++) v += red[w][tid];
        int p = m >> 1;  // pair index: ang = i * 10000^(-p/512)
        float ang = (float)tid * expf(-(float)p * (9.210340371976184f / 512.0f));
        v += (m & 1) ? cosf(ang) : sinf(ang);
        g_s0[tid * M_ + m] = v;
        atomicAdd(&g_ln1[(tid * TKA + 0) * 2 + 0], v);
        atomicAdd(&g_ln1[(tid * TKA + 0) * 2 + 1], v * v);
    }
}

// ---------------- main persistent kernel ----------------
__global__ void __launch_bounds__(NTHR, 1) k_main(
    const float* __restrict__ Wv,   const float* __restrict__ Wo,
    const float* __restrict__ ln1g, const float* __restrict__ ln1b,
    const float* __restrict__ ln2g, const float* __restrict__ ln2b,
    const float* __restrict__ fc1w, const float* __restrict__ fc1b,
    const float* __restrict__ fc2w, const float* __restrict__ fc2b,
    float* __restrict__ out)
{
    __shared__ float sh[H_];        // 32 KB activation staging
    __shared__ float shp[NWB];      // per-warp partials (K-split combine)
    __shared__ float red2[2];
    const int tid = threadIdx.x, lane = tid & 31, wid = tid >> 5;
    const int gw = blockIdx.x * NWB + wid;       // global warp id [0, 4736)
    const float4* shv = (const float4*)sh;
    unsigned barph = 0;

    for (int i = 0; i < TKN; i++) {
        for (int a = 0; a < TKA; a++) {
            const float* svec = (a == 0) ? (g_s0 + i * M_) : g_s;

            // ---- phase V: vcum[a] += Wv[a] @ LN1(s)   (q,k dead: softmax(1)=1)
            // 2-way K-split: task gw<4096 -> (row=gw>>1, half=gw&1), K=1024 each.
            {
                float ssum = __ldcg(&g_ln1[(i * TKA + a) * 2 + 0]);
                float ssq  = __ldcg(&g_ln1[(i * TKA + a) * 2 + 1]);
                float mu = ssum * (1.0f / M_);
                float var = fmaxf(ssq * (1.0f / M_) - mu * mu, 0.f);
                float rstd = rsqrtf(var + 1e-5f);
                for (int m = tid; m < M_; m += NTHR) {
                    float xx = __ldcg(&svec[m]);
                    sh[m] = (xx - mu) * rstd * ln1g[m] + ln1b[m];
                }
                __syncthreads();
                float part = 0.f;
                if (gw < 2 * M_) {
                    int row = gw >> 1, half = gw & 1;
                    const float4* wr = (const float4*)(Wv + (size_t)a * M_ * M_ + (size_t)row * M_) + half * 256;
                    const float4* xv = shv + half * 256;
#pragma unroll
                    for (int kk = 0; kk < 8; kk++) {
                        float4 w = wr[lane + kk * 32];
                        float4 x = xv[lane + kk * 32];
                        part = fmaf(w.x, x.x, fmaf(w.y, x.y, fmaf(w.z, x.z, fmaf(w.w, x.w, part))));
                    }
                    part = wredsum(part);
                }
                if (lane == 0) shp[wid] = part;
                __syncthreads();
                if ((wid & 1) == 0 && gw < 2 * M_ && lane == 0) {
                    int row = gw >> 1;
                    float acc = shp[wid] + shp[wid + 1];
                    __stcg(&g_vcum[a * M_ + row], __ldcg(&g_vcum[a * M_ + row]) + acc);
                }
            }
            gbar(++barph * NBLK);

            // ---- phase Wo: s' = Wo[a] @ vcum[a] + s ; emit LN2 stats ----
            {
                if (tid < 2) red2[tid] = 0.f;
                for (int m = tid; m < M_; m += NTHR) sh[m] = __ldcg(&g_vcum[a * M_ + m]);
                __syncthreads();
                float part = 0.f;
                if (gw < 2 * M_) {
                    int row = gw >> 1, half = gw & 1;
                    const float4* wr = (const float4*)(Wo + (size_t)a * M_ * M_ + (size_t)row * M_) + half * 256;
                    const float4* xv = shv + half * 256;
#pragma unroll
                    for (int kk = 0; kk < 8; kk++) {
                        float4 w = wr[lane + kk * 32];
                        float4 x = xv[lane + kk * 32];
                        part = fmaf(w.x, x.x, fmaf(w.y, x.y, fmaf(w.z, x.z, fmaf(w.w, x.w, part))));
                    }
                    part = wredsum(part);
                }
                if (lane == 0) shp[wid] = part;
                __syncthreads();
                if ((wid & 1) == 0 && gw < 2 * M_ && lane == 0) {
                    int row = gw >> 1;
                    float acc = shp[wid] + shp[wid + 1] + __ldcg(&svec[row]);
                    __stcg(&g_sp[row], acc);
                    atomicAdd(&red2[0], acc);
                    atomicAdd(&red2[1], acc * acc);
                }
                __syncthreads();
                if (tid == 0) {
                    atomicAdd(&g_ln2[(i * TKA + a) * 2 + 0], red2[0]);
                    atomicAdd(&g_ln2[(i * TKA + a) * 2 + 1], red2[1]);
                }
            }
            gbar(++barph * NBLK);

            // ---- phase fc1: h = gelu(fc1 @ (LN2(s') + s') + b1) : rows gw, gw+NWARP
            {
                float ssum = __ldcg(&g_ln2[(i * TKA + a) * 2 + 0]);
                float ssq  = __ldcg(&g_ln2[(i * TKA + a) * 2 + 1]);
                float mu = ssum * (1.0f / M_);
                float var = fmaxf(ssq * (1.0f / M_) - mu * mu, 0.f);
                float rstd = rsqrtf(var + 1e-5f);
                for (int m = tid; m < M_; m += NTHR) {
                    float sp = __ldcg(&g_sp[m]);
                    sh[m] = (sp - mu) * rstd * ln2g[m] + ln2b[m] + sp;
                }
                __syncthreads();
#pragma unroll
                for (int rr = 0; rr < 2; rr++) {
                    int r = gw + rr * NWARP;
                    if (r < H_) {
                        const float4* wr = (const float4*)(fc1w + (size_t)r * M_);
                        float acc = 0.f;
#pragma unroll
                        for (int kk = 0; kk < 16; kk++) {
                            float4 w = wr[lane + kk * 32];
                            float4 x = shv[lane + kk * 32];
                            acc = fmaf(w.x, x.x, fmaf(w.y, x.y, fmaf(w.z, x.z, fmaf(w.w, x.w, acc))));
                        }
                        acc = wredsum(acc);
                        if (lane == 0) {
                            acc += fc1b[r];
                            float g = 0.5f * acc * (1.0f + erff(acc * 0.70710678118654752f));
                            __stcg(&g_h[r], g);
                        }
                    }
                }
            }
            gbar(++barph * NBLK);

            // ---- phase fc2: s_next = fc2 @ h + b2 ; 2-way K-split (K=4096 each)
            {
                if (tid < 2) red2[tid] = 0.f;
                {
                    float4* s4 = (float4*)sh;
                    const float4* h4 = (const float4*)g_h;
                    for (int m = tid; m < H_ / 4; m += NTHR) s4[m] = __ldcg(&h4[m]);
                }
                __syncthreads();
                float part = 0.f;
                if (gw < 2 * M_) {
                    int row = gw >> 1, half = gw & 1;
                    const float4* wr = (const float4*)(fc2w + (size_t)row * H_) + half * 1024;
                    const float4* xv = shv + half * 1024;
                    for (int k0 = 0; k0 < 32; k0 += 8) {
#pragma unroll
                        for (int kk = 0; kk < 8; kk++) {
                            float4 w = wr[lane + (k0 + kk) * 32];
                            float4 x = xv[lane + (k0 + kk) * 32];
                            part = fmaf(w.x, x.x, fmaf(w.y, x.y, fmaf(w.z, x.z, fmaf(w.w, x.w, part))));
                        }
                    }
                    part = wredsum(part);
                }
                if (lane == 0) shp[wid] = part;
                __syncthreads();
                if ((wid & 1) == 0 && gw < 2 * M_ && lane == 0) {
                    int row = gw >> 1;
                    float acc = shp[wid] + shp[wid + 1] + fc2b[row];
                    if (a == TKA - 1) {
                        out[i * M_ + row] = acc;
                    } else {
                        __stcg(&g_s[row], acc);
                        atomicAdd(&red2[0], acc);
                        atomicAdd(&red2[1], acc * acc);
                    }
                }
                if (a < TKA - 1) {
                    __syncthreads();
                    if (tid == 0) {
                        atomicAdd(&g_ln1[(i * TKA + a + 1) * 2 + 0], red2[0]);
                        atomicAdd(&g_ln1[(i * TKA + a + 1) * 2 + 1], red2[1]);
                    }
                }
            }
            gbar(++barph * NBLK);
        }
    }
}

// ---------------- launch ----------------
extern "C" void kernel_launch(void* const* d_in, const int* in_sizes, int n_in,
                              void* d_out, int out_size) {
    const float* x      = (const float*)d_in[0];
    const float* weight = (const float*)d_in[1];
    // d_in[2] = Wq, d_in[3] = Wk: dead code (softmax over size-1 axis == 1)
    const float* Wv     = (const float*)d_in[4];
    const float* Wo     = (const float*)d_in[5];
    const float* ln1g   = (const float*)d_in[6];
    const float* ln1b   = (const float*)d_in[7];
    const float* ln2g   = (const float*)d_in[8];
    const float* ln2b   = (const float*)d_in[9];
    const float* fc1w   = (const float*)d_in[10];
    const float* fc1b   = (const float*)d_in[11];
    const float* fc2w   = (const float*)d_in[12];
    const float* fc2b   = (const float*)d_in[13];
    float* out = (float*)d_out;

    k_init<<<1, 256>>>();
    k_xcf<<<(TKN * M_ + 255) / 256, 256>>>(x);
    k_s0<<<M_, 256>>>(weight);
    k_main<<<NBLK, NTHR>>>(Wv, Wo, ln1g, ln1b, ln2g, ln2b,
                           fc1w, fc1b, fc2w, fc2b, out);
}

// round 5
// speedup vs baseline: 10.0495x; 5.0215x over previous
#include <cuda_runtime.h>
#include <cstdint>

#define NBLK 148
#define NTHR 1024
#define NWB  32
#define NWARP (NBLK * NWB)      // 4736
#define M_   2048
#define H_   8192
#define TKN  32
#define TKA  3
#define KC   32                 // K-chunk staged per iteration
#define TILE_R 128              // rows per GEMM tile
#define WS_STRIDE 132           // 128 rows + 4 pad (bank spread, 16B aligned)
#define GSM_XS (KC * WS_STRIDE)         // 4224
#define GSM_LNP (GSM_XS + KC * TKN)     // 5248
#define GSM_SIZE (GSM_LNP + 64)         // 5312 floats per group

// ---------------- persistent device state ----------------
__device__ float g_xcfT[M_ * TKN];      // [k][token]
__device__ float g_sT  [M_ * TKN];      // current s, [row][token]
__device__ float g_spT [M_ * TKN];      // s' after Wo+residual
__device__ float g_vcT [M_ * TKN];      // vcum (prefix-summed v)
__device__ float g_hT  [H_ * TKN];      // gelu(fc1...)
__device__ float g_part[16 * M_ * TKN]; // K-split partials (4 MB; fc1 uses [4][H_][32])
__device__ float g_ln1s[TKA][64];       // per-round LN1 stats: [sum[32], sumsq[32]]
__device__ float g_ln2s[TKA][64];
__device__ unsigned g_ctr;

// ---------------- global barrier ----------------
__device__ __forceinline__ void gbar(unsigned target) {
    __threadfence();
    __syncthreads();
    if (threadIdx.x == 0) {
        atomicAdd(&g_ctr, 1u);
        unsigned v;
        do {
            asm volatile("ld.global.acquire.gpu.u32 %0, [%1];"
                         : "=r"(v) : "l"(&g_ctr) : "memory");
            if (v < target) __nanosleep(64);
        } while (v < target);
    }
    __syncthreads();
}

// group-scoped barrier (512 threads, named barrier id = group+1)
__device__ __forceinline__ void gsync(int group) {
    asm volatile("bar.sync %0, %1;" :: "r"(group + 1), "r"(512) : "memory");
}

// packed fp32x2 FMA (Blackwell FFMA2)
__device__ __forceinline__ void ffma2(unsigned long long& d, unsigned long long a, unsigned long long b) {
    asm("fma.rn.f32x2 %0, %1, %2, %0;" : "+l"(d) : "l"(a), "l"(b));
}
__device__ __forceinline__ unsigned long long packff(float x) {
    unsigned long long r; unsigned xb = __float_as_uint(x);
    asm("mov.b64 %0, {%1, %1};" : "=l"(r) : "r"(xb));
    return r;
}
__device__ __forceinline__ float2 unpk(unsigned long long v) {
    unsigned lo, hi;
    asm("mov.b64 {%0, %1}, %2;" : "=r"(lo), "=r"(hi) : "l"(v));
    return make_float2(__uint_as_float(lo), __uint_as_float(hi));
}

// ---------------- prologue kernels ----------------
__global__ void k_init() {
    int t = threadIdx.x;
    if (t == 0) g_ctr = 0u;
    if (t < TKA * 64) {
        ((float*)g_ln1s)[t] = 0.f;
        ((float*)g_ln2s)[t] = 0.f;
    }
}

// xcfT[m][i] = mean over 16 consecutive t of x[ab,b,i*16+t], m = b*16+ab
__global__ void k_xcf(const float* __restrict__ x) {
    int idx = blockIdx.x * blockDim.x + threadIdx.x;
    if (idx >= TKN * M_) return;
    int i = idx >> 11, m = idx & 2047;
    int b = m >> 4, ab = m & 15;
    const float* p = x + ab * (128 * 512) + b * 512 + i * 16;
    float s = 0.f;
#pragma unroll
    for (int t = 0; t < 16; t++) s += p[t];
    g_xcfT[m * TKN + i] = s * (1.0f / 16.0f);
}

// ---------------- GEMM phase: P[ks][r][c] (+)= W[r][k0..]*X[k0..][c] ----------------
// mode: 0 raw, 1 LN1(x), 2 LN2(x)+x.  Tile: 128 rows x 32 cols; thread 4x2 (f32x2 row pairs).
__device__ __forceinline__ void gemm_phase(
    float* gs, const float* __restrict__ W, const float* __restrict__ Xg,
    const float* __restrict__ lng, const float* __restrict__ lnb,
    const float* __restrict__ stat, int mode,
    int Kfull, int KS, int ksplit, int ntiles, int rowstot,
    int bid, int group, int tid2)
{
    float* Ws  = gs;             // [KC][WS_STRIDE] transposed: Ws[k][row]
    float* Xs  = gs + GSM_XS;    // [KC][32]
    float* lnp = gs + GSM_LNP;   // mu[32], rstd[32]
    if (mode != 0) {
        if (tid2 < 32) {
            float s = stat[tid2], q = stat[32 + tid2];
            float mu = s * (1.0f / M_);
            float var = fmaxf(q * (1.0f / M_) - mu * mu, 0.f);
            lnp[tid2] = mu;
            lnp[32 + tid2] = rsqrtf(var + 1e-5f);
        }
        gsync(group);
    }
    const int srow = tid2 >> 2, skq = tid2 & 3;      // W staging: row, k-octet
    const int xk = tid2 >> 4, xc = (tid2 & 15) * 2;  // X staging
    const int tr = tid2 >> 4, tc = tid2 & 15;        // compute: 4 rows (tr*4), 2 cols (tc*2)
    const int ntasks = ntiles * ksplit;

    for (int task = group * NBLK + bid; task < ntasks; task += 2 * NBLK) {
        int rt = task / ksplit, ks = task - rt * ksplit;
        int r0 = rt * TILE_R, k0 = ks * KS;
        unsigned long long a00 = 0, a10 = 0, a01 = 0, a11 = 0;

        for (int kc = k0; kc < k0 + KS; kc += KC) {
            // stage W transposed (global row-major read, smem [k][row] store)
            {
                const float4* wp = (const float4*)(W + (size_t)(r0 + srow) * Kfull + kc + skq * 8);
                float4 v0 = wp[0], v1 = wp[1];
                int kb = skq * 8;
                Ws[(kb + 0) * WS_STRIDE + srow] = v0.x;
                Ws[(kb + 1) * WS_STRIDE + srow] = v0.y;
                Ws[(kb + 2) * WS_STRIDE + srow] = v0.z;
                Ws[(kb + 3) * WS_STRIDE + srow] = v0.w;
                Ws[(kb + 4) * WS_STRIDE + srow] = v1.x;
                Ws[(kb + 5) * WS_STRIDE + srow] = v1.y;
                Ws[(kb + 6) * WS_STRIDE + srow] = v1.z;
                Ws[(kb + 7) * WS_STRIDE + srow] = v1.w;
            }
            // stage X (fused LN transform)
            {
                float2 xv = *(const float2*)(Xg + (size_t)(kc + xk) * TKN + xc);
                if (mode != 0) {
                    float gk = lng[kc + xk], bk = lnb[kc + xk];
                    float n0 = (xv.x - lnp[xc])     * lnp[32 + xc]     * gk + bk;
                    float n1 = (xv.y - lnp[xc + 1]) * lnp[33 + xc]     * gk + bk;
                    if (mode == 2) { n0 += xv.x; n1 += xv.y; }
                    xv.x = n0; xv.y = n1;
                }
                *(float2*)(Xs + xk * TKN + xc) = xv;
            }
            gsync(group);
#pragma unroll 8
            for (int kk = 0; kk < KC; kk++) {
                unsigned long long w01 = *(const unsigned long long*)(Ws + kk * WS_STRIDE + tr * 4);
                unsigned long long w23 = *(const unsigned long long*)(Ws + kk * WS_STRIDE + tr * 4 + 2);
                unsigned long long xx0 = packff(Xs[kk * TKN + tc * 2]);
                unsigned long long xx1 = packff(Xs[kk * TKN + tc * 2 + 1]);
                ffma2(a00, w01, xx0);
                ffma2(a10, w23, xx0);
                ffma2(a01, w01, xx1);
                ffma2(a11, w23, xx1);
            }
            gsync(group);
        }
        float2 r01c0 = unpk(a00), r23c0 = unpk(a10);
        float2 r01c1 = unpk(a01), r23c1 = unpk(a11);
        float* pp = g_part + ((size_t)ks * rowstot + r0 + tr * 4) * TKN + tc * 2;
        *(float2*)(pp + 0 * TKN) = make_float2(r01c0.x, r01c1.x);
        *(float2*)(pp + 1 * TKN) = make_float2(r01c0.y, r01c1.y);
        *(float2*)(pp + 2 * TKN) = make_float2(r23c0.x, r23c1.x);
        *(float2*)(pp + 3 * TKN) = make_float2(r23c0.y, r23c1.y);
    }
}

// ---------------- main persistent kernel ----------------
__global__ void __launch_bounds__(NTHR, 1) k_main(
    const float* __restrict__ weight,
    const float* __restrict__ Wv,   const float* __restrict__ Wo,
    const float* __restrict__ ln1g, const float* __restrict__ ln1b,
    const float* __restrict__ ln2g, const float* __restrict__ ln2b,
    const float* __restrict__ fc1w, const float* __restrict__ fc1b,
    const float* __restrict__ fc2w, const float* __restrict__ fc2b,
    float* __restrict__ out)
{
    __shared__ float gs[2][GSM_SIZE];
    __shared__ float sm_stat[64];
    const int tid = threadIdx.x, lane = tid & 31, wid = tid >> 5;
    const int bid = blockIdx.x;
    const int group = tid >> 9, tid2 = tid & 511;
    const int gw = bid * NWB + wid;
    unsigned ph = 0;

    // ---- s0 GEMM: part[ks] = weight-tile @ xcfT ----
    gemm_phase(gs[group], weight, g_xcfT, nullptr, nullptr, nullptr, 0,
               M_, 128, 16, 16, M_, bid, group, tid2);
    gbar(++ph * NBLK);

    // ---- C_s0: s0 = sum(part) + positional bias ; LN1 stats round 0 ----
    {
        if (tid < 64) sm_stat[tid] = 0.f;
        __syncthreads();
        for (int row = gw; row < M_; row += NWARP) {
            float v = 0.f;
#pragma unroll
            for (int ksl = 0; ksl < 16; ksl++)
                v += g_part[((size_t)ksl * M_ + row) * TKN + lane];
            int p = row >> 1;
            float ang = (float)lane * expf(-(float)p * (9.210340371976184f / 512.0f));
            v += (row & 1) ? cosf(ang) : sinf(ang);
            g_sT[row * TKN + lane] = v;
            atomicAdd(&sm_stat[lane], v);
            atomicAdd(&sm_stat[32 + lane], v * v);
        }
        __syncthreads();
        if (tid < 64) atomicAdd(&((float*)g_ln1s)[tid], sm_stat[tid]);
    }
    gbar(++ph * NBLK);

    for (int a = 0; a < TKA; a++) {
        // ---- G1: v = Wv[a] @ LN1(s) ----
        gemm_phase(gs[group], Wv + (size_t)a * M_ * M_, g_sT, ln1g, ln1b,
                   g_ln1s[a], 1, M_, 128, 16, 16, M_, bid, group, tid2);
        gbar(++ph * NBLK);

        // ---- C1: vcum = prefix-sum over tokens ----
        for (int row = gw; row < M_; row += NWARP) {
            float v = 0.f;
#pragma unroll
            for (int ksl = 0; ksl < 16; ksl++)
                v += g_part[((size_t)ksl * M_ + row) * TKN + lane];
#pragma unroll
            for (int o = 1; o < 32; o <<= 1) {
                float n = __shfl_up_sync(0xffffffffu, v, o);
                if (lane >= o) v += n;
            }
            g_vcT[row * TKN + lane] = v;
        }
        gbar(++ph * NBLK);

        // ---- G2: Wo[a] @ vcum ----
        gemm_phase(gs[group], Wo + (size_t)a * M_ * M_, g_vcT, nullptr, nullptr,
                   nullptr, 0, M_, 128, 16, 16, M_, bid, group, tid2);
        gbar(++ph * NBLK);

        // ---- C2: s' = sum + s ; LN2 stats ----
        {
            if (tid < 64) sm_stat[tid] = 0.f;
            __syncthreads();
            for (int row = gw; row < M_; row += NWARP) {
                float v = 0.f;
#pragma unroll
                for (int ksl = 0; ksl < 16; ksl++)
                    v += g_part[((size_t)ksl * M_ + row) * TKN + lane];
                v += g_sT[row * TKN + lane];
                g_spT[row * TKN + lane] = v;
                atomicAdd(&sm_stat[lane], v);
                atomicAdd(&sm_stat[32 + lane], v * v);
            }
            __syncthreads();
            if (tid < 64) atomicAdd(&g_ln2s[a][tid], sm_stat[tid]);
        }
        gbar(++ph * NBLK);

        // ---- G3: fc1 @ (LN2(s')+s') ----
        gemm_phase(gs[group], fc1w, g_spT, ln2g, ln2b, g_ln2s[a], 2,
                   M_, 512, 4, 64, H_, bid, group, tid2);
        gbar(++ph * NBLK);

        // ---- C3: h = gelu(sum + b1) ----
        for (int row = gw; row < H_; row += NWARP) {
            float v = 0.f;
#pragma unroll
            for (int ksl = 0; ksl < 4; ksl++)
                v += g_part[((size_t)ksl * H_ + row) * TKN + lane];
            v += fc1b[row];
            v = 0.5f * v * (1.0f + erff(v * 0.70710678118654752f));
            g_hT[row * TKN + lane] = v;
        }
        gbar(++ph * NBLK);

        // ---- G4: fc2 @ h ----
        gemm_phase(gs[group], fc2w, g_hT, nullptr, nullptr, nullptr, 0,
                   H_, 512, 16, 16, M_, bid, group, tid2);
        gbar(++ph * NBLK);

        // ---- C4: s_next = sum + b2 ; output or LN1 stats for next round ----
        {
            if (tid < 64) sm_stat[tid] = 0.f;
            __syncthreads();
            for (int row = gw; row < M_; row += NWARP) {
                float v = 0.f;
#pragma unroll
                for (int ksl = 0; ksl < 16; ksl++)
                    v += g_part[((size_t)ksl * M_ + row) * TKN + lane];
                v += fc2b[row];
                if (a == TKA - 1) {
                    out[lane * M_ + row] = v;
                } else {
                    g_sT[row * TKN + lane] = v;
                    atomicAdd(&sm_stat[lane], v);
                    atomicAdd(&sm_stat[32 + lane], v * v);
                }
            }
            __syncthreads();
            if (a < TKA - 1 && tid < 64) atomicAdd(&g_ln1s[a + 1][tid], sm_stat[tid]);
        }
        gbar(++ph * NBLK);
    }
}

// ---------------- launch ----------------
extern "C" void kernel_launch(void* const* d_in, const int* in_sizes, int n_in,
                              void* d_out, int out_size) {
    const float* x      = (const float*)d_in[0];
    const float* weight = (const float*)d_in[1];
    // d_in[2] = Wq, d_in[3] = Wk: dead code (softmax over size-1 axis == 1)
    const float* Wv     = (const float*)d_in[4];
    const float* Wo     = (const float*)d_in[5];
    const float* ln1g   = (const float*)d_in[6];
    const float* ln1b   = (const float*)d_in[7];
    const float* ln2g   = (const float*)d_in[8];
    const float* ln2b   = (const float*)d_in[9];
    const float* fc1w   = (const float*)d_in[10];
    const float* fc1b   = (const float*)d_in[11];
    const float* fc2w   = (const float*)d_in[12];
    const float* fc2b   = (const float*)d_in[13];
    float* out = (float*)d_out;

    k_init<<<1, 256>>>();
    k_xcf<<<(TKN * M_ + 255) / 256, 256>>>(x);
    k_main<<<NBLK, NTHR>>>(weight, Wv, Wo, ln1g, ln1b, ln2g, ln2b,
                           fc1w, fc1b, fc2w, fc2b, out);
}

// round 6
// speedup vs baseline: 12.4172x; 1.2356x over previous
#include <cuda_runtime.h>
#include <cstdint>

#define NBLK 148
#define NTHR 1024
#define NWB  32
#define NWARP (NBLK * NWB)      // 4736
#define GT   256                // threads per GEMM group
#define NG   4                  // groups per block
#define NGRP (NBLK * NG)        // 592 groups
#define M_   2048
#define H_   8192
#define TKN  32
#define TKA  3
#define KC   32                 // K-chunk
#define TILE_R 128
#define WST  130                // Ws row stride (even -> LDS64 aligned)
#define XST  36
#define WS_FLOATS (KC * WST)            // 4160
#define XS_FLOATS (KC * XST)            // 1152
#define GRP_FLOATS (WS_FLOATS + XS_FLOATS)  // 5312
#define SMEM_BYTES (NG * GRP_FLOATS * 4)    // 84992

typedef unsigned long long ull;

// ---------------- persistent device state ----------------
__device__ float g_xcfT[M_ * TKN];      // [k][token]
__device__ float g_sT  [M_ * TKN];
__device__ float g_spT [M_ * TKN];
__device__ float g_vcT [M_ * TKN];
__device__ float g_hT  [H_ * TKN];
__device__ float g_part[32 * M_ * TKN]; // K-split partials (8.4 MB, L2-resident)
__device__ float g_ln1s[TKA][64];
__device__ float g_ln2s[TKA][64];
__device__ unsigned g_ctr;

// ---------------- barriers ----------------
__device__ __forceinline__ void gbar(unsigned target) {
    __threadfence();
    __syncthreads();
    if (threadIdx.x == 0) {
        atomicAdd(&g_ctr, 1u);
        unsigned v;
        do {
            asm volatile("ld.global.acquire.gpu.u32 %0, [%1];"
                         : "=r"(v) : "l"(&g_ctr) : "memory");
            if (v < target) __nanosleep(64);
        } while (v < target);
    }
    __syncthreads();
}
__device__ __forceinline__ void gsync(int group) {
    asm volatile("bar.sync %0, %1;" :: "r"(group + 1), "r"(GT) : "memory");
}

// packed fp32x2 helpers
__device__ __forceinline__ void ffma2(ull& d, ull a, ull b) {
    asm("fma.rn.f32x2 %0, %1, %2, %0;" : "+l"(d) : "l"(a), "l"(b));
}
__device__ __forceinline__ ull packff(float x) {
    ull r; unsigned xb = __float_as_uint(x);
    asm("mov.b64 %0, {%1, %1};" : "=l"(r) : "r"(xb));
    return r;
}
__device__ __forceinline__ float2 unpk(ull v) {
    unsigned lo, hi;
    asm("mov.b64 {%0, %1}, %2;" : "=r"(lo), "=r"(hi) : "l"(v));
    return make_float2(__uint_as_float(lo), __uint_as_float(hi));
}

// ---------------- prologue ----------------
__global__ void k_init() {
    int t = threadIdx.x;
    if (t == 0) g_ctr = 0u;
    if (t < TKA * 64) { ((float*)g_ln1s)[t] = 0.f; ((float*)g_ln2s)[t] = 0.f; }
}

__global__ void k_xcf(const float* __restrict__ x) {
    int idx = blockIdx.x * blockDim.x + threadIdx.x;
    if (idx >= TKN * M_) return;
    int i = idx >> 11, m = idx & 2047;
    int b = m >> 4, ab = m & 15;
    const float* p = x + ab * (128 * 512) + b * 512 + i * 16;
    float s = 0.f;
#pragma unroll
    for (int t = 0; t < 16; t++) s += p[t];
    g_xcfT[m * TKN + i] = s * (1.0f / 16.0f);
}

// ---------------- GEMM phase (register-double-buffered) ----------------
// mode: 0 raw, 1 LN1(x), 2 LN2(x)+x. Tile 128x32; thread: 8 rows x 2 tokens.
__device__ __forceinline__ void gemm_phase(
    float* Ws, float* Xs, float* lnp,
    const float* __restrict__ W, const float* __restrict__ Xg,
    const float* __restrict__ lng, const float* __restrict__ lnb,
    const float* __restrict__ stat, int mode,
    int Kfull, int KS, int ksplit, int ntiles, int rowstot,
    int gidx, int group, int tid2)
{
    if (mode != 0) {
        if (threadIdx.x < 32) {
            float s = __ldcg(&stat[threadIdx.x]), q = __ldcg(&stat[32 + threadIdx.x]);
            float mu = s * (1.0f / M_);
            float var = fmaxf(q * (1.0f / M_) - mu * mu, 0.f);
            lnp[threadIdx.x] = mu;
            lnp[32 + threadIdx.x] = rsqrtf(var + 1e-5f);
        }
        __syncthreads();
    }
    const int srow = tid2 >> 1, shalf = tid2 & 1;     // W staging: 128 rows x 2 k-halves
    const int sk = tid2 >> 3, st4 = (tid2 & 7) * 4;   // X staging: 32 k x 8 token-quads
    const int tr = tid2 >> 4, tc = tid2 & 15;         // compute: rows tr*8.., tokens tc*2..
    const int ntasks = ntiles * ksplit;
    const int nchunk = KS / KC;

    for (int task = gidx; task < ntasks; task += NGRP) {
        int rt = task / ksplit, ks = task - rt * ksplit;
        int r0 = rt * TILE_R, k0 = ks * KS;
        ull a00 = 0, a01 = 0, a10 = 0, a11 = 0, a20 = 0, a21 = 0, a30 = 0, a31 = 0;

        // prefetch chunk 0
        float4 w0, w1, w2, w3, xr;
        {
            const float4* wp = (const float4*)(W + (size_t)(r0 + srow) * Kfull + k0 + shalf * 16);
            w0 = __ldcs(wp); w1 = __ldcs(wp + 1); w2 = __ldcs(wp + 2); w3 = __ldcs(wp + 3);
            xr = __ldcg((const float4*)(Xg + (size_t)(k0 + sk) * TKN + st4));
        }

        for (int c = 0; c < nchunk; c++) {
            gsync(group);                 // prior compute done reading smem
            // store W transposed
            {
                int kb = shalf * 16;
                Ws[(kb + 0)  * WST + srow] = w0.x;
                Ws[(kb + 1)  * WST + srow] = w0.y;
                Ws[(kb + 2)  * WST + srow] = w0.z;
                Ws[(kb + 3)  * WST + srow] = w0.w;
                Ws[(kb + 4)  * WST + srow] = w1.x;
                Ws[(kb + 5)  * WST + srow] = w1.y;
                Ws[(kb + 6)  * WST + srow] = w1.z;
                Ws[(kb + 7)  * WST + srow] = w1.w;
                Ws[(kb + 8)  * WST + srow] = w2.x;
                Ws[(kb + 9)  * WST + srow] = w2.y;
                Ws[(kb + 10) * WST + srow] = w2.z;
                Ws[(kb + 11) * WST + srow] = w2.w;
                Ws[(kb + 12) * WST + srow] = w3.x;
                Ws[(kb + 13) * WST + srow] = w3.y;
                Ws[(kb + 14) * WST + srow] = w3.z;
                Ws[(kb + 15) * WST + srow] = w3.w;
            }
            // store X (fused LN)
            {
                float4 xv = xr;
                if (mode != 0) {
                    float gk = lng[k0 + c * KC + sk], bk = lnb[k0 + c * KC + sk];
                    float n0 = (xv.x - lnp[st4 + 0]) * lnp[32 + st4 + 0] * gk + bk;
                    float n1 = (xv.y - lnp[st4 + 1]) * lnp[32 + st4 + 1] * gk + bk;
                    float n2 = (xv.z - lnp[st4 + 2]) * lnp[32 + st4 + 2] * gk + bk;
                    float n3 = (xv.w - lnp[st4 + 3]) * lnp[32 + st4 + 3] * gk + bk;
                    if (mode == 2) { n0 += xv.x; n1 += xv.y; n2 += xv.z; n3 += xv.w; }
                    xv = make_float4(n0, n1, n2, n3);
                }
                *(float4*)(Xs + sk * XST + st4) = xv;
            }
            // prefetch next chunk into regs (overlaps following compute)
            if (c + 1 < nchunk) {
                const float4* wp = (const float4*)(W + (size_t)(r0 + srow) * Kfull + k0 + (c + 1) * KC + shalf * 16);
                w0 = __ldcs(wp); w1 = __ldcs(wp + 1); w2 = __ldcs(wp + 2); w3 = __ldcs(wp + 3);
                xr = __ldcg((const float4*)(Xg + (size_t)(k0 + (c + 1) * KC + sk) * TKN + st4));
            }
            gsync(group);                 // staging visible
            // compute
            const float* wbase = Ws + tr * 8;
            const float* xbase = Xs + tc * 2;
#pragma unroll
            for (int kk = 0; kk < KC; kk++) {
                ull wp0 = *(const ull*)(wbase + kk * WST + 0);
                ull wp1 = *(const ull*)(wbase + kk * WST + 2);
                ull wp2 = *(const ull*)(wbase + kk * WST + 4);
                ull wp3 = *(const ull*)(wbase + kk * WST + 6);
                ull xx0 = packff(xbase[kk * XST]);
                ull xx1 = packff(xbase[kk * XST + 1]);
                ffma2(a00, wp0, xx0); ffma2(a01, wp0, xx1);
                ffma2(a10, wp1, xx0); ffma2(a11, wp1, xx1);
                ffma2(a20, wp2, xx0); ffma2(a21, wp2, xx1);
                ffma2(a30, wp3, xx0); ffma2(a31, wp3, xx1);
            }
        }
        // write partials: rows r0+tr*8 .. +7, tokens tc*2, tc*2+1
        float* pp = g_part + ((size_t)ks * rowstot + r0 + tr * 8) * TKN + tc * 2;
        float2 p0c0 = unpk(a00), p0c1 = unpk(a01);
        float2 p1c0 = unpk(a10), p1c1 = unpk(a11);
        float2 p2c0 = unpk(a20), p2c1 = unpk(a21);
        float2 p3c0 = unpk(a30), p3c1 = unpk(a31);
        __stcg((float2*)(pp + 0 * TKN), make_float2(p0c0.x, p0c1.x));
        __stcg((float2*)(pp + 1 * TKN), make_float2(p0c0.y, p0c1.y));
        __stcg((float2*)(pp + 2 * TKN), make_float2(p1c0.x, p1c1.x));
        __stcg((float2*)(pp + 3 * TKN), make_float2(p1c0.y, p1c1.y));
        __stcg((float2*)(pp + 4 * TKN), make_float2(p2c0.x, p2c1.x));
        __stcg((float2*)(pp + 5 * TKN), make_float2(p2c0.y, p2c1.y));
        __stcg((float2*)(pp + 6 * TKN), make_float2(p3c0.x, p3c1.x));
        __stcg((float2*)(pp + 7 * TKN), make_float2(p3c0.y, p3c1.y));
    }
}

// combine helper: sum NS partials for (row, lane)
template <int NS>
__device__ __forceinline__ float psum(int rowstot, int row, int lane) {
    float v = 0.f;
#pragma unroll
    for (int ksl = 0; ksl < NS; ksl++)
        v += __ldcg(&g_part[((size_t)ksl * rowstot + row) * TKN + lane]);
    return v;
}

// ---------------- main persistent kernel ----------------
__global__ void __launch_bounds__(NTHR, 1) k_main(
    const float* __restrict__ weight,
    const float* __restrict__ Wv,   const float* __restrict__ Wo,
    const float* __restrict__ ln1g, const float* __restrict__ ln1b,
    const float* __restrict__ ln2g, const float* __restrict__ ln2b,
    const float* __restrict__ fc1w, const float* __restrict__ fc1b,
    const float* __restrict__ fc2w, const float* __restrict__ fc2b,
    float* __restrict__ out)
{
    extern __shared__ float dsm[];
    __shared__ float lnp[64];
    __shared__ float sm_stat[64];
    const int tid = threadIdx.x, lane = tid & 31, wid = tid >> 5;
    const int bid = blockIdx.x;
    const int group = tid >> 8, tid2 = tid & (GT - 1);
    const int gidx = bid * NG + group;
    const int gw = bid * NWB + wid;
    float* Ws = dsm + group * GRP_FLOATS;
    float* Xs = Ws + WS_FLOATS;
    unsigned ph = 0;

    // ---- s0 GEMM ----
    gemm_phase(Ws, Xs, lnp, weight, g_xcfT, nullptr, nullptr, nullptr, 0,
               M_, 64, 32, 16, M_, gidx, group, tid2);
    gbar(++ph * NBLK);

    // ---- C_s0: s0 = sum(32 partials) + positional bias ; LN1 stats round 0 ----
    {
        if (tid < 64) sm_stat[tid] = 0.f;
        __syncthreads();
        for (int row = gw; row < M_; row += NWARP) {
            float v = psum<32>(M_, row, lane);
            int p = row >> 1;
            float ang = (float)lane * expf(-(float)p * (9.210340371976184f / 512.0f));
            v += (row & 1) ? cosf(ang) : sinf(ang);
            __stcg(&g_sT[row * TKN + lane], v);
            atomicAdd(&sm_stat[lane], v);
            atomicAdd(&sm_stat[32 + lane], v * v);
        }
        __syncthreads();
        if (tid < 64) atomicAdd(&((float*)g_ln1s)[tid], sm_stat[tid]);
    }
    gbar(++ph * NBLK);

    for (int a = 0; a < TKA; a++) {
        // ---- G1: v = Wv[a] @ LN1(s) ----
        gemm_phase(Ws, Xs, lnp, Wv + (size_t)a * M_ * M_, g_sT, ln1g, ln1b,
                   g_ln1s[a], 1, M_, 64, 32, 16, M_, gidx, group, tid2);
        gbar(++ph * NBLK);

        // ---- C1: vcum = prefix-sum over tokens ----
        for (int row = gw; row < M_; row += NWARP) {
            float v = psum<32>(M_, row, lane);
#pragma unroll
            for (int o = 1; o < 32; o <<= 1) {
                float n = __shfl_up_sync(0xffffffffu, v, o);
                if (lane >= o) v += n;
            }
            __stcg(&g_vcT[row * TKN + lane], v);
        }
        gbar(++ph * NBLK);

        // ---- G2: Wo[a] @ vcum ----
        gemm_phase(Ws, Xs, lnp, Wo + (size_t)a * M_ * M_, g_vcT, nullptr, nullptr,
                   nullptr, 0, M_, 64, 32, 16, M_, gidx, group, tid2);
        gbar(++ph * NBLK);

        // ---- C2: s' = sum + s ; LN2 stats ----
        {
            if (tid < 64) sm_stat[tid] = 0.f;
            __syncthreads();
            for (int row = gw; row < M_; row += NWARP) {
                float v = psum<32>(M_, row, lane) + __ldcg(&g_sT[row * TKN + lane]);
                __stcg(&g_spT[row * TKN + lane], v);
                atomicAdd(&sm_stat[lane], v);
                atomicAdd(&sm_stat[32 + lane], v * v);
            }
            __syncthreads();
            if (tid < 64) atomicAdd(&g_ln2s[a][tid], sm_stat[tid]);
        }
        gbar(++ph * NBLK);

        // ---- G3: fc1 @ (LN2(s')+s') ----
        gemm_phase(Ws, Xs, lnp, fc1w, g_spT, ln2g, ln2b, g_ln2s[a], 2,
                   M_, 256, 8, 64, H_, gidx, group, tid2);
        gbar(++ph * NBLK);

        // ---- C3: h = gelu(sum + b1) ----
        for (int row = gw; row < H_; row += NWARP) {
            float v = psum<8>(H_, row, lane) + fc1b[row];
            v = 0.5f * v * (1.0f + erff(v * 0.70710678118654752f));
            __stcg(&g_hT[row * TKN + lane], v);
        }
        gbar(++ph * NBLK);

        // ---- G4: fc2 @ h ----
        gemm_phase(Ws, Xs, lnp, fc2w, g_hT, nullptr, nullptr, nullptr, 0,
                   H_, 256, 32, 16, M_, gidx, group, tid2);
        gbar(++ph * NBLK);

        // ---- C4: s_next = sum + b2 ; output or next-round LN1 stats ----
        {
            if (tid < 64) sm_stat[tid] = 0.f;
            __syncthreads();
            for (int row = gw; row < M_; row += NWARP) {
                float v = psum<32>(M_, row, lane) + fc2b[row];
                if (a == TKA - 1) {
                    out[lane * M_ + row] = v;
                } else {
                    __stcg(&g_sT[row * TKN + lane], v);
                    atomicAdd(&sm_stat[lane], v);
                    atomicAdd(&sm_stat[32 + lane], v * v);
                }
            }
            __syncthreads();
            if (a < TKA - 1 && tid < 64) atomicAdd(&g_ln1s[a + 1][tid], sm_stat[tid]);
        }
        gbar(++ph * NBLK);
    }
}

// ---------------- launch ----------------
extern "C" void kernel_launch(void* const* d_in, const int* in_sizes, int n_in,
                              void* d_out, int out_size) {
    const float* x      = (const float*)d_in[0];
    const float* weight = (const float*)d_in[1];
    // d_in[2] = Wq, d_in[3] = Wk: dead (softmax over size-1 axis == 1)
    const float* Wv     = (const float*)d_in[4];
    const float* Wo     = (const float*)d_in[5];
    const float* ln1g   = (const float*)d_in[6];
    const float* ln1b   = (const float*)d_in[7];
    const float* ln2g   = (const float*)d_in[8];
    const float* ln2b   = (const float*)d_in[9];
    const float* fc1w   = (const float*)d_in[10];
    const float* fc1b   = (const float*)d_in[11];
    const float* fc2w   = (const float*)d_in[12];
    const float* fc2b   = (const float*)d_in[13];
    float* out = (float*)d_out;

    static int smem_set = 0;
    if (!smem_set) {
        cudaFuncSetAttribute(k_main, cudaFuncAttributeMaxDynamicSharedMemorySize, SMEM_BYTES);
        smem_set = 1;
    }
    k_init<<<1, 256>>>();
    k_xcf<<<(TKN * M_ + 255) / 256, 256>>>(x);
    k_main<<<NBLK, NTHR, SMEM_BYTES>>>(weight, Wv, Wo, ln1g, ln1b, ln2g, ln2b,
                                       fc1w, fc1b, fc2w, fc2b, out);
}

// round 7
// speedup vs baseline: 16.3405x; 1.3160x over previous
#include <cuda_runtime.h>
#include <cstdint>

#define NBLK 148
#define NTHR 1024
#define NWB  32
#define NWARP (NBLK * NWB)      // 4736
#define GT   256                // threads per GEMM group
#define NG   4                  // groups per block
#define NGRP (NBLK * NG)        // 592 groups
#define M_   2048
#define H_   8192
#define TKN  32
#define TKA  3
#define KC   32                 // K-chunk
#define TILE_R 128
#define WST  130                // Ws row stride in floats
#define XSU  33                 // Xs row stride in ull (8B units)
#define WS_FLOATS (KC * WST)            // 4160
#define XS_FLOATS (KC * XSU * 2)        // 2112 floats (ull-packed)
#define GRP_FLOATS (WS_FLOATS + XS_FLOATS)  // 6272
#define SMEM_BYTES (NG * GRP_FLOATS * 4)    // 100352

typedef unsigned long long ull;

// ---------------- persistent device state ----------------
__device__ float g_xcfT[M_ * TKN];      // [k][token]
__device__ float g_sT  [M_ * TKN];
__device__ float g_spT [M_ * TKN];
__device__ float g_vcT [M_ * TKN];
__device__ float g_hT  [H_ * TKN];
__device__ float g_part[32 * M_ * TKN]; // K-split partials (8.4 MB, L2-resident)
__device__ float g_ln1s[TKA][64];
__device__ float g_ln2s[TKA][64];
__device__ unsigned g_cnt;              // sense-reversing barrier: arrival count
__device__ unsigned g_gen;              // generation (monotone across replays)

// ---------------- grid barrier (sense-reversing; survives graph replays) ----
__device__ __forceinline__ void gbar() {
    __syncthreads();
    if (threadIdx.x == 0) {
        unsigned my;
        asm volatile("ld.global.relaxed.gpu.u32 %0, [%1];" : "=r"(my) : "l"(&g_gen));
        unsigned old;
        asm volatile("atom.global.add.acq_rel.gpu.u32 %0, [%1], 1;"
                     : "=r"(old) : "l"(&g_cnt));
        if (old == NBLK - 1) {
            unsigned z = 0;
            asm volatile("st.global.relaxed.gpu.u32 [%0], %1;" :: "l"(&g_cnt), "r"(z));
            asm volatile("red.global.add.release.gpu.u32 [%0], %1;" :: "l"(&g_gen), "r"(1u));
        } else {
            unsigned cur;
            do {
                asm volatile("ld.global.acquire.gpu.u32 %0, [%1];" : "=r"(cur) : "l"(&g_gen));
                if (cur == my) __nanosleep(32);
            } while (cur == my);
        }
    }
    __syncthreads();
}
__device__ __forceinline__ void gsync(int group) {
    asm volatile("bar.sync %0, %1;" :: "r"(group + 1), "r"(GT) : "memory");
}

// packed fp32x2 helpers
__device__ __forceinline__ void ffma2(ull& d, ull a, ull b) {
    asm("fma.rn.f32x2 %0, %1, %2, %0;" : "+l"(d) : "l"(a), "l"(b));
}
__device__ __forceinline__ ull dup2(float x) {
    ull r; unsigned xb = __float_as_uint(x);
    asm("mov.b64 %0, {%1, %1};" : "=l"(r) : "r"(xb));
    return r;
}
__device__ __forceinline__ float2 unpk(ull v) {
    unsigned lo, hi;
    asm("mov.b64 {%0, %1}, %2;" : "=r"(lo), "=r"(hi) : "l"(v));
    return make_float2(__uint_as_float(lo), __uint_as_float(hi));
}

// ---------------- GEMM phase (register-double-buffered) ----------------
// mode: 0 raw, 1 LN1(x), 2 LN2(x)+x. Tile 128x32; thread: 8 rows x tokens {tc, tc+16}.
__device__ __forceinline__ void gemm_phase(
    float* Ws, ull* Xs, float* lnp,
    const float* __restrict__ W, const float* __restrict__ Xg,
    const float* __restrict__ lng, const float* __restrict__ lnb,
    const float* __restrict__ stat, int mode,
    int Kfull, int KS, int ksplit, int ntiles, int rowstot,
    int gidx, int group, int tid2)
{
    if (mode != 0) {
        if (threadIdx.x < 32) {
            float s = __ldcg(&stat[threadIdx.x]), q = __ldcg(&stat[32 + threadIdx.x]);
            float mu = s * (1.0f / M_);
            float var = fmaxf(q * (1.0f / M_) - mu * mu, 0.f);
            lnp[threadIdx.x] = mu;
            lnp[32 + threadIdx.x] = rsqrtf(var + 1e-5f);
        }
        __syncthreads();
    }
    const int srow = tid2 >> 1, shalf = tid2 & 1;     // W staging
    const int sk = tid2 >> 3, st4 = (tid2 & 7) * 4;   // X staging
    const int tr = tid2 >> 4, tc = tid2 & 15;         // compute
    const int ntasks = ntiles * ksplit;
    const int nchunk = KS / KC;

    for (int task = gidx; task < ntasks; task += NGRP) {
        int rt = task / ksplit, ks = task - rt * ksplit;
        int r0 = rt * TILE_R, k0 = ks * KS;
        ull a00 = 0, a01 = 0, a10 = 0, a11 = 0, a20 = 0, a21 = 0, a30 = 0, a31 = 0;

        // prefetch chunk 0
        float4 w0, w1, w2, w3, xr;
        {
            const float4* wp = (const float4*)(W + (size_t)(r0 + srow) * Kfull + k0 + shalf * 16);
            w0 = __ldcs(wp); w1 = __ldcs(wp + 1); w2 = __ldcs(wp + 2); w3 = __ldcs(wp + 3);
            xr = __ldcg((const float4*)(Xg + (size_t)(k0 + sk) * TKN + st4));
        }

        for (int c = 0; c < nchunk; c++) {
            gsync(group);
            // store W transposed
            {
                int kb = shalf * 16;
                Ws[(kb + 0)  * WST + srow] = w0.x;
                Ws[(kb + 1)  * WST + srow] = w0.y;
                Ws[(kb + 2)  * WST + srow] = w0.z;
                Ws[(kb + 3)  * WST + srow] = w0.w;
                Ws[(kb + 4)  * WST + srow] = w1.x;
                Ws[(kb + 5)  * WST + srow] = w1.y;
                Ws[(kb + 6)  * WST + srow] = w1.z;
                Ws[(kb + 7)  * WST + srow] = w1.w;
                Ws[(kb + 8)  * WST + srow] = w2.x;
                Ws[(kb + 9)  * WST + srow] = w2.y;
                Ws[(kb + 10) * WST + srow] = w2.z;
                Ws[(kb + 11) * WST + srow] = w2.w;
                Ws[(kb + 12) * WST + srow] = w3.x;
                Ws[(kb + 13) * WST + srow] = w3.y;
                Ws[(kb + 14) * WST + srow] = w3.z;
                Ws[(kb + 15) * WST + srow] = w3.w;
            }
            // store X (fused LN), pre-duplicated f32x2
            {
                float4 xv = xr;
                if (mode != 0) {
                    float gk = lng[k0 + c * KC + sk], bk = lnb[k0 + c * KC + sk];
                    float n0 = (xv.x - lnp[st4 + 0]) * lnp[32 + st4 + 0] * gk + bk;
                    float n1 = (xv.y - lnp[st4 + 1]) * lnp[32 + st4 + 1] * gk + bk;
                    float n2 = (xv.z - lnp[st4 + 2]) * lnp[32 + st4 + 2] * gk + bk;
                    float n3 = (xv.w - lnp[st4 + 3]) * lnp[32 + st4 + 3] * gk + bk;
                    if (mode == 2) { n0 += xv.x; n1 += xv.y; n2 += xv.z; n3 += xv.w; }
                    xv = make_float4(n0, n1, n2, n3);
                }
                ull* xd = Xs + sk * XSU + st4;
                xd[0] = dup2(xv.x); xd[1] = dup2(xv.y);
                xd[2] = dup2(xv.z); xd[3] = dup2(xv.w);
            }
            // prefetch next chunk
            if (c + 1 < nchunk) {
                const float4* wp = (const float4*)(W + (size_t)(r0 + srow) * Kfull + k0 + (c + 1) * KC + shalf * 16);
                w0 = __ldcs(wp); w1 = __ldcs(wp + 1); w2 = __ldcs(wp + 2); w3 = __ldcs(wp + 3);
                xr = __ldcg((const float4*)(Xg + (size_t)(k0 + (c + 1) * KC + sk) * TKN + st4));
            }
            gsync(group);
            // compute: 14 instrs / 16 MACs
            const float* wbase = Ws + tr * 8;
            const ull* xbase = Xs + tc;
#pragma unroll
            for (int kk = 0; kk < KC; kk++) {
                ull wp0 = *(const ull*)(wbase + kk * WST + 0);
                ull wp1 = *(const ull*)(wbase + kk * WST + 2);
                ull wp2 = *(const ull*)(wbase + kk * WST + 4);
                ull wp3 = *(const ull*)(wbase + kk * WST + 6);
                ull xx0 = xbase[kk * XSU];        // token tc
                ull xx1 = xbase[kk * XSU + 16];   // token tc+16
                ffma2(a00, wp0, xx0); ffma2(a01, wp0, xx1);
                ffma2(a10, wp1, xx0); ffma2(a11, wp1, xx1);
                ffma2(a20, wp2, xx0); ffma2(a21, wp2, xx1);
                ffma2(a30, wp3, xx0); ffma2(a31, wp3, xx1);
            }
        }
        // write partials: rows r0+tr*8..+7, tokens tc and tc+16
        float* pp = g_part + ((size_t)ks * rowstot + r0 + tr * 8) * TKN;
        float2 c0, c1;
        c0 = unpk(a00); c1 = unpk(a01);
        __stcg(pp + 0 * TKN + tc, c0.x); __stcg(pp + 0 * TKN + tc + 16, c1.x);
        __stcg(pp + 1 * TKN + tc, c0.y); __stcg(pp + 1 * TKN + tc + 16, c1.y);
        c0 = unpk(a10); c1 = unpk(a11);
        __stcg(pp + 2 * TKN + tc, c0.x); __stcg(pp + 2 * TKN + tc + 16, c1.x);
        __stcg(pp + 3 * TKN + tc, c0.y); __stcg(pp + 3 * TKN + tc + 16, c1.y);
        c0 = unpk(a20); c1 = unpk(a21);
        __stcg(pp + 4 * TKN + tc, c0.x); __stcg(pp + 4 * TKN + tc + 16, c1.x);
        __stcg(pp + 5 * TKN + tc, c0.y); __stcg(pp + 5 * TKN + tc + 16, c1.y);
        c0 = unpk(a30); c1 = unpk(a31);
        __stcg(pp + 6 * TKN + tc, c0.x); __stcg(pp + 6 * TKN + tc + 16, c1.x);
        __stcg(pp + 7 * TKN + tc, c0.y); __stcg(pp + 7 * TKN + tc + 16, c1.y);
    }
}

// combine helper
template <int NS>
__device__ __forceinline__ float psum(int rowstot, int row, int lane) {
    float v = 0.f;
#pragma unroll
    for (int ksl = 0; ksl < NS; ksl++)
        v += __ldcg(&g_part[((size_t)ksl * rowstot + row) * TKN + lane]);
    return v;
}

// ---------------- single persistent kernel ----------------
__global__ void __launch_bounds__(NTHR, 1) k_main(
    const float* __restrict__ x,
    const float* __restrict__ weight,
    const float* __restrict__ Wv,   const float* __restrict__ Wo,
    const float* __restrict__ ln1g, const float* __restrict__ ln1b,
    const float* __restrict__ ln2g, const float* __restrict__ ln2b,
    const float* __restrict__ fc1w, const float* __restrict__ fc1b,
    const float* __restrict__ fc2w, const float* __restrict__ fc2b,
    float* __restrict__ out)
{
    extern __shared__ float dsm[];
    __shared__ float lnp[64];
    __shared__ float sm_stat[64];
    const int tid = threadIdx.x, lane = tid & 31, wid = tid >> 5;
    const int bid = blockIdx.x;
    const int group = tid >> 8, tid2 = tid & (GT - 1);
    const int gidx = bid * NG + group;
    const int gw = bid * NWB + wid;
    float* Ws = dsm + group * GRP_FLOATS;
    ull*   Xs = (ull*)(Ws + WS_FLOATS);

    // ---- P0: prologue — xcf + zero LN stats ----
    {
        int idx = bid * NTHR + tid;
        if (idx < TKN * M_) {
            int i = idx >> 11, m = idx & 2047;
            int b = m >> 4, ab = m & 15;
            const float* p = x + ab * (128 * 512) + b * 512 + i * 16;
            float s = 0.f;
#pragma unroll
            for (int t = 0; t < 16; t++) s += p[t];
            __stcg(&g_xcfT[m * TKN + i], s * (1.0f / 16.0f));
        }
        if (bid == 0 && tid < TKA * 64) {
            __stcg(&((float*)g_ln1s)[tid], 0.f);
            __stcg(&((float*)g_ln2s)[tid], 0.f);
        }
    }
    gbar();

    // ---- s0 GEMM ----
    gemm_phase(Ws, Xs, lnp, weight, g_xcfT, nullptr, nullptr, nullptr, 0,
               M_, 64, 32, 16, M_, gidx, group, tid2);
    gbar();

    // ---- C_s0: s0 = sum + positional bias ; LN1 stats round 0 ----
    {
        if (tid < 64) sm_stat[tid] = 0.f;
        __syncthreads();
        for (int row = gw; row < M_; row += NWARP) {
            float v = psum<32>(M_, row, lane);
            int p = row >> 1;
            float ang = (float)lane * expf(-(float)p * (9.210340371976184f / 512.0f));
            v += (row & 1) ? cosf(ang) : sinf(ang);
            __stcg(&g_sT[row * TKN + lane], v);
            atomicAdd(&sm_stat[lane], v);
            atomicAdd(&sm_stat[32 + lane], v * v);
        }
        __syncthreads();
        if (tid < 64) atomicAdd(&((float*)g_ln1s)[tid], sm_stat[tid]);
    }
    gbar();

    for (int a = 0; a < TKA; a++) {
        // ---- G1: v = Wv[a] @ LN1(s) ----
        gemm_phase(Ws, Xs, lnp, Wv + (size_t)a * M_ * M_, g_sT, ln1g, ln1b,
                   g_ln1s[a], 1, M_, 64, 32, 16, M_, gidx, group, tid2);
        gbar();

        // ---- C1: vcum = prefix-sum over tokens ----
        for (int row = gw; row < M_; row += NWARP) {
            float v = psum<32>(M_, row, lane);
#pragma unroll
            for (int o = 1; o < 32; o <<= 1) {
                float n = __shfl_up_sync(0xffffffffu, v, o);
                if (lane >= o) v += n;
            }
            __stcg(&g_vcT[row * TKN + lane], v);
        }
        gbar();

        // ---- G2: Wo[a] @ vcum ----
        gemm_phase(Ws, Xs, lnp, Wo + (size_t)a * M_ * M_, g_vcT, nullptr, nullptr,
                   nullptr, 0, M_, 64, 32, 16, M_, gidx, group, tid2);
        gbar();

        // ---- C2: s' = sum + s ; LN2 stats ----
        {
            if (tid < 64) sm_stat[tid] = 0.f;
            __syncthreads();
            for (int row = gw; row < M_; row += NWARP) {
                float v = psum<32>(M_, row, lane) + __ldcg(&g_sT[row * TKN + lane]);
                __stcg(&g_spT[row * TKN + lane], v);
                atomicAdd(&sm_stat[lane], v);
                atomicAdd(&sm_stat[32 + lane], v * v);
            }
            __syncthreads();
            if (tid < 64) atomicAdd(&g_ln2s[a][tid], sm_stat[tid]);
        }
        gbar();

        // ---- G3: fc1 @ (LN2(s')+s') ----
        gemm_phase(Ws, Xs, lnp, fc1w, g_spT, ln2g, ln2b, g_ln2s[a], 2,
                   M_, 256, 8, 64, H_, gidx, group, tid2);
        gbar();

        // ---- C3: h = gelu(sum + b1) ----
        for (int row = gw; row < H_; row += NWARP) {
            float v = psum<8>(H_, row, lane) + fc1b[row];
            v = 0.5f * v * (1.0f + erff(v * 0.70710678118654752f));
            __stcg(&g_hT[row * TKN + lane], v);
        }
        gbar();

        // ---- G4: fc2 @ h ----
        gemm_phase(Ws, Xs, lnp, fc2w, g_hT, nullptr, nullptr, nullptr, 0,
                   H_, 256, 32, 16, M_, gidx, group, tid2);
        gbar();

        // ---- C4: s_next = sum + b2 ; output or next-round LN1 stats ----
        {
            if (tid < 64) sm_stat[tid] = 0.f;
            __syncthreads();
            for (int row = gw; row < M_; row += NWARP) {
                float v = psum<32>(M_, row, lane) + fc2b[row];
                if (a == TKA - 1) {
                    out[lane * M_ + row] = v;
                } else {
                    __stcg(&g_sT[row * TKN + lane], v);
                    atomicAdd(&sm_stat[lane], v);
                    atomicAdd(&sm_stat[32 + lane], v * v);
                }
            }
            __syncthreads();
            if (a < TKA - 1 && tid < 64) atomicAdd(&g_ln1s[a + 1][tid], sm_stat[tid]);
        }
        gbar();
    }
}

// ---------------- launch ----------------
extern "C" void kernel_launch(void* const* d_in, const int* in_sizes, int n_in,
                              void* d_out, int out_size) {
    const float* x      = (const float*)d_in[0];
    const float* weight = (const float*)d_in[1];
    // d_in[2] = Wq, d_in[3] = Wk: dead (softmax over size-1 axis == 1)
    const float* Wv     = (const float*)d_in[4];
    const float* Wo     = (const float*)d_in[5];
    const float* ln1g   = (const float*)d_in[6];
    const float* ln1b   = (const float*)d_in[7];
    const float* ln2g   = (const float*)d_in[8];
    const float* ln2b   = (const float*)d_in[9];
    const float* fc1w   = (const float*)d_in[10];
    const float* fc1b   = (const float*)d_in[11];
    const float* fc2w   = (const float*)d_in[12];
    const float* fc2b   = (const float*)d_in[13];
    float* out = (float*)d_out;

    static int smem_set = 0;
    if (!smem_set) {
        cudaFuncSetAttribute(k_main, cudaFuncAttributeMaxDynamicSharedMemorySize, SMEM_BYTES);
        smem_set = 1;
    }
    k_main<<<NBLK, NTHR, SMEM_BYTES>>>(x, weight, Wv, Wo, ln1g, ln1b, ln2g, ln2b,
                                       fc1w, fc1b, fc2w, fc2b, out);
}

// round 10
// speedup vs baseline: 16.3923x; 1.0032x over previous
#include <cuda_runtime.h>
#include <cstdint>

#define NBLK 148
#define NTHR 1024
#define NWB  32
#define NWARP (NBLK * NWB)      // 4736
#define GT   256                // threads per GEMM group
#define NG   4                  // groups per block
#define NGRP (NBLK * NG)        // 592 groups
#define M_   2048
#define H_   8192
#define TKN  32
#define TKA  3
#define KC   32                 // K-chunk
#define TILE_R 128
#define WST  132                // Ws row stride in floats (16B-aligned rows)
#define XSU  34                 // Xs row stride in ull (16B-aligned rows)
#define WS_FLOATS (KC * WST)            // 4224
#define XS_FLOATS (KC * XSU * 2)        // 2176 floats (ull-packed)
#define GRP_FLOATS (WS_FLOATS + XS_FLOATS)  // 6400
#define SMEM_BYTES (NG * GRP_FLOATS * 4)    // 102400

typedef unsigned long long ull;

// ---------------- persistent device state ----------------
__device__ float g_xcfT[M_ * TKN];      // [k][token]
__device__ float g_sT  [M_ * TKN];
__device__ float g_spT [M_ * TKN];
__device__ float g_vcT [M_ * TKN];
__device__ float g_hT  [H_ * TKN];
__device__ float g_part[32 * M_ * TKN]; // K-split partials (8.4 MB, L2-resident)
__device__ float g_ln1s[TKA][64];
__device__ float g_ln2s[TKA][64];
__device__ unsigned g_cnt;              // sense-reversing barrier: arrival count
__device__ unsigned g_gen;              // generation (monotone across replays)

// ---------------- grid barrier (sense-reversing; survives graph replays) ----
__device__ __forceinline__ void gbar() {
    __syncthreads();
    if (threadIdx.x == 0) {
        unsigned my;
        asm volatile("ld.global.relaxed.gpu.u32 %0, [%1];" : "=r"(my) : "l"(&g_gen));
        unsigned old;
        asm volatile("atom.global.add.acq_rel.gpu.u32 %0, [%1], 1;"
                     : "=r"(old) : "l"(&g_cnt));
        if (old == NBLK - 1) {
            unsigned z = 0;
            asm volatile("st.global.relaxed.gpu.u32 [%0], %1;" :: "l"(&g_cnt), "r"(z));
            asm volatile("red.global.add.release.gpu.u32 [%0], %1;" :: "l"(&g_gen), "r"(1u));
        } else {
            unsigned cur;
            do {
                asm volatile("ld.global.acquire.gpu.u32 %0, [%1];" : "=r"(cur) : "l"(&g_gen));
                if (cur == my) __nanosleep(32);
            } while (cur == my);
        }
    }
    __syncthreads();
}
__device__ __forceinline__ void gsync(int group) {
    asm volatile("bar.sync %0, %1;" :: "r"(group + 1), "r"(GT) : "memory");
}

// packed fp32x2 helpers
__device__ __forceinline__ void ffma2(ull& d, ull a, ull b) {
    asm("fma.rn.f32x2 %0, %1, %2, %0;" : "+l"(d) : "l"(a), "l"(b));
}
__device__ __forceinline__ ull dup2(float x) {
    ull r; unsigned xb = __float_as_uint(x);
    asm("mov.b64 %0, {%1, %1};" : "=l"(r) : "r"(xb));
    return r;
}
__device__ __forceinline__ float2 unpk(ull v) {
    unsigned lo, hi;
    asm("mov.b64 {%0, %1}, %2;" : "=r"(lo), "=r"(hi) : "l"(v));
    return make_float2(__uint_as_float(lo), __uint_as_float(hi));
}

// ---------------- GEMM phase (register-double-buffered, LDS128 inner) ------
// mode: 0 raw, 1 LN1(x), 2 LN2(x)+x. Tile 128x32; thread: 8 rows x tokens {2tc, 2tc+1}.
__device__ __forceinline__ void gemm_phase(
    float* Ws, ull* Xs, float* lnp,
    const float* __restrict__ W, const float* __restrict__ Xg,
    const float* __restrict__ lng, const float* __restrict__ lnb,
    const float* __restrict__ stat, int mode,
    int Kfull, int KS, int ksplit, int ntiles, int rowstot,
    int gidx, int group, int tid2)
{
    if (mode != 0) {
        if (threadIdx.x < 32) {
            float s = __ldcg(&stat[threadIdx.x]), q = __ldcg(&stat[32 + threadIdx.x]);
            float mu = s * (1.0f / M_);
            float var = fmaxf(q * (1.0f / M_) - mu * mu, 0.f);
            lnp[threadIdx.x] = mu;
            lnp[32 + threadIdx.x] = rsqrtf(var + 1e-5f);
        }
        __syncthreads();
    }
    const int srow = tid2 >> 1, shalf = tid2 & 1;     // W staging
    const int sk = tid2 >> 3, st4 = (tid2 & 7) * 4;   // X staging
    const int tr = tid2 >> 4, tc = tid2 & 15;         // compute
    const int ntasks = ntiles * ksplit;
    const int nchunk = KS / KC;

    for (int task = gidx; task < ntasks; task += NGRP) {
        int rt = task / ksplit, ks = task - rt * ksplit;
        int r0 = rt * TILE_R, k0 = ks * KS;
        ull a00 = 0, a01 = 0, a10 = 0, a11 = 0, a20 = 0, a21 = 0, a30 = 0, a31 = 0;

        // prefetch chunk 0
        float4 w0, w1, w2, w3, xr;
        {
            const float4* wp = (const float4*)(W + (size_t)(r0 + srow) * Kfull + k0 + shalf * 16);
            w0 = __ldcs(wp); w1 = __ldcs(wp + 1); w2 = __ldcs(wp + 2); w3 = __ldcs(wp + 3);
            xr = __ldcg((const float4*)(Xg + (size_t)(k0 + sk) * TKN + st4));
        }

        for (int c = 0; c < nchunk; c++) {
            gsync(group);
            // store W transposed
            {
                int kb = shalf * 16;
                Ws[(kb + 0)  * WST + srow] = w0.x;
                Ws[(kb + 1)  * WST + srow] = w0.y;
                Ws[(kb + 2)  * WST + srow] = w0.z;
                Ws[(kb + 3)  * WST + srow] = w0.w;
                Ws[(kb + 4)  * WST + srow] = w1.x;
                Ws[(kb + 5)  * WST + srow] = w1.y;
                Ws[(kb + 6)  * WST + srow] = w1.z;
                Ws[(kb + 7)  * WST + srow] = w1.w;
                Ws[(kb + 8)  * WST + srow] = w2.x;
                Ws[(kb + 9)  * WST + srow] = w2.y;
                Ws[(kb + 10) * WST + srow] = w2.z;
                Ws[(kb + 11) * WST + srow] = w2.w;
                Ws[(kb + 12) * WST + srow] = w3.x;
                Ws[(kb + 13) * WST + srow] = w3.y;
                Ws[(kb + 14) * WST + srow] = w3.z;
                Ws[(kb + 15) * WST + srow] = w3.w;
            }
            // store X (fused LN), pre-duplicated f32x2 pairs
            {
                float4 xv = xr;
                if (mode != 0) {
                    float gk = lng[k0 + c * KC + sk], bk = lnb[k0 + c * KC + sk];
                    float n0 = (xv.x - lnp[st4 + 0]) * lnp[32 + st4 + 0] * gk + bk;
                    float n1 = (xv.y - lnp[st4 + 1]) * lnp[32 + st4 + 1] * gk + bk;
                    float n2 = (xv.z - lnp[st4 + 2]) * lnp[32 + st4 + 2] * gk + bk;
                    float n3 = (xv.w - lnp[st4 + 3]) * lnp[32 + st4 + 3] * gk + bk;
                    if (mode == 2) { n0 += xv.x; n1 += xv.y; n2 += xv.z; n3 += xv.w; }
                    xv = make_float4(n0, n1, n2, n3);
                }
                ull* xd = Xs + sk * XSU + st4;
                xd[0] = dup2(xv.x); xd[1] = dup2(xv.y);
                xd[2] = dup2(xv.z); xd[3] = dup2(xv.w);
            }
            // prefetch next chunk
            if (c + 1 < nchunk) {
                const float4* wp = (const float4*)(W + (size_t)(r0 + srow) * Kfull + k0 + (c + 1) * KC + shalf * 16);
                w0 = __ldcs(wp); w1 = __ldcs(wp + 1); w2 = __ldcs(wp + 2); w3 = __ldcs(wp + 3);
                xr = __ldcg((const float4*)(Xg + (size_t)(k0 + (c + 1) * KC + sk) * TKN + st4));
            }
            gsync(group);
            // compute: 3 LDS128 + 8 FFMA2 per kk
            const float* wbase = Ws + tr * 8;
            const ull*   xbase = Xs + tc * 2;
#pragma unroll
            for (int kk = 0; kk < KC; kk++) {
                longlong2 wA = *(const longlong2*)(wbase + kk * WST);       // rows 0-3
                longlong2 wB = *(const longlong2*)(wbase + kk * WST + 4);   // rows 4-7
                longlong2 xx = *(const longlong2*)(xbase + kk * XSU);       // tokens 2tc, 2tc+1
                ffma2(a00, (ull)wA.x, (ull)xx.x); ffma2(a01, (ull)wA.x, (ull)xx.y);
                ffma2(a10, (ull)wA.y, (ull)xx.x); ffma2(a11, (ull)wA.y, (ull)xx.y);
                ffma2(a20, (ull)wB.x, (ull)xx.x); ffma2(a21, (ull)wB.x, (ull)xx.y);
                ffma2(a30, (ull)wB.y, (ull)xx.x); ffma2(a31, (ull)wB.y, (ull)xx.y);
            }
        }
        // write partials: rows r0+tr*8..+7, tokens 2tc, 2tc+1 (adjacent -> STG.64)
        float* pp = g_part + ((size_t)ks * rowstot + r0 + tr * 8) * TKN + tc * 2;
        float2 c0, c1;
        c0 = unpk(a00); c1 = unpk(a01);
        __stcg((float2*)(pp + 0 * TKN), make_float2(c0.x, c1.x));
        __stcg((float2*)(pp + 1 * TKN), make_float2(c0.y, c1.y));
        c0 = unpk(a10); c1 = unpk(a11);
        __stcg((float2*)(pp + 2 * TKN), make_float2(c0.x, c1.x));
        __stcg((float2*)(pp + 3 * TKN), make_float2(c0.y, c1.y));
        c0 = unpk(a20); c1 = unpk(a21);
        __stcg((float2*)(pp + 4 * TKN), make_float2(c0.x, c1.x));
        __stcg((float2*)(pp + 5 * TKN), make_float2(c0.y, c1.y));
        c0 = unpk(a30); c1 = unpk(a31);
        __stcg((float2*)(pp + 6 * TKN), make_float2(c0.x, c1.x));
        __stcg((float2*)(pp + 7 * TKN), make_float2(c0.y, c1.y));
    }
}

// combine helper
template <int NS>
__device__ __forceinline__ float psum(int rowstot, int row, int lane) {
    float v = 0.f;
#pragma unroll
    for (int ksl = 0; ksl < NS; ksl++)
        v += __ldcg(&g_part[((size_t)ksl * rowstot + row) * TKN + lane]);
    return v;
}

// ---------------- single persistent kernel ----------------
__global__ void __launch_bounds__(NTHR, 1) k_main(
    const float* __restrict__ x,
    const float* __restrict__ weight,
    const float* __restrict__ Wv,   const float* __restrict__ Wo,
    const float* __restrict__ ln1g, const float* __restrict__ ln1b,
    const float* __restrict__ ln2g, const float* __restrict__ ln2b,
    const float* __restrict__ fc1w, const float* __restrict__ fc1b,
    const float* __restrict__ fc2w, const float* __restrict__ fc2b,
    float* __restrict__ out)
{
    extern __shared__ float dsm[];
    __shared__ float lnp[64];
    __shared__ float sm_stat[64];
    const int tid = threadIdx.x, lane = tid & 31, wid = tid >> 5;
    const int bid = blockIdx.x;
    const int group = tid >> 8, tid2 = tid & (GT - 1);
    const int gidx = bid * NG + group;
    const int gw = bid * NWB + wid;
    float* Ws = dsm + group * GRP_FLOATS;
    ull*   Xs = (ull*)(Ws + WS_FLOATS);

    // ---- P0: prologue — xcf + zero LN stats ----
    {
        int idx = bid * NTHR + tid;
        if (idx < TKN * M_) {
            int i = idx >> 11, m = idx & 2047;
            int b = m >> 4, ab = m & 15;
            const float* p = x + ab * (128 * 512) + b * 512 + i * 16;
            float s = 0.f;
#pragma unroll
            for (int t = 0; t < 16; t++) s += p[t];
            __stcg(&g_xcfT[m * TKN + i], s * (1.0f / 16.0f));
        }
        if (bid == 0 && tid < TKA * 64) {
            __stcg(&((float*)g_ln1s)[tid], 0.f);
            __stcg(&((float*)g_ln2s)[tid], 0.f);
        }
    }
    gbar();

    // ---- s0 GEMM ----
    gemm_phase(Ws, Xs, lnp, weight, g_xcfT, nullptr, nullptr, nullptr, 0,
               M_, 64, 32, 16, M_, gidx, group, tid2);
    gbar();

    // ---- C_s0: s0 = sum + positional bias ; LN1 stats round 0 ----
    {
        if (tid < 64) sm_stat[tid] = 0.f;
        __syncthreads();
        for (int row = gw; row < M_; row += NWARP) {
            float v = psum<32>(M_, row, lane);
            int p = row >> 1;
            float ang = (float)lane * expf(-(float)p * (9.210340371976184f / 512.0f));
            v += (row & 1) ? cosf(ang) : sinf(ang);
            __stcg(&g_sT[row * TKN + lane], v);
            atomicAdd(&sm_stat[lane], v);
            atomicAdd(&sm_stat[32 + lane], v * v);
        }
        __syncthreads();
        if (tid < 64) atomicAdd(&((float*)g_ln1s)[tid], sm_stat[tid]);
    }
    gbar();

    for (int a = 0; a < TKA; a++) {
        // ---- G1: v = Wv[a] @ LN1(s) ----
        gemm_phase(Ws, Xs, lnp, Wv + (size_t)a * M_ * M_, g_sT, ln1g, ln1b,
                   g_ln1s[a], 1, M_, 64, 32, 16, M_, gidx, group, tid2);
        gbar();

        // ---- C1: vcum = prefix-sum over tokens ----
        for (int row = gw; row < M_; row += NWARP) {
            float v = psum<32>(M_, row, lane);
#pragma unroll
            for (int o = 1; o < 32; o <<= 1) {
                float n = __shfl_up_sync(0xffffffffu, v, o);
                if (lane >= o) v += n;
            }
            __stcg(&g_vcT[row * TKN + lane], v);
        }
        gbar();

        // ---- G2: Wo[a] @ vcum ----
        gemm_phase(Ws, Xs, lnp, Wo + (size_t)a * M_ * M_, g_vcT, nullptr, nullptr,
                   nullptr, 0, M_, 64, 32, 16, M_, gidx, group, tid2);
        gbar();

        // ---- C2: s' = sum + s ; LN2 stats ----
        {
            if (tid < 64) sm_stat[tid] = 0.f;
            __syncthreads();
            for (int row = gw; row < M_; row += NWARP) {
                float v = psum<32>(M_, row, lane) + __ldcg(&g_sT[row * TKN + lane]);
                __stcg(&g_spT[row * TKN + lane], v);
                atomicAdd(&sm_stat[lane], v);
                atomicAdd(&sm_stat[32 + lane], v * v);
            }
            __syncthreads();
            if (tid < 64) atomicAdd(&g_ln2s[a][tid], sm_stat[tid]);
        }
        gbar();

        // ---- G3: fc1 @ (LN2(s')+s') ----
        gemm_phase(Ws, Xs, lnp, fc1w, g_spT, ln2g, ln2b, g_ln2s[a], 2,
                   M_, 256, 8, 64, H_, gidx, group, tid2);
        gbar();

        // ---- C3: h = gelu(sum + b1) ----
        for (int row = gw; row < H_; row += NWARP) {
            float v = psum<8>(H_, row, lane) + fc1b[row];
            v = 0.5f * v * (1.0f + erff(v * 0.70710678118654752f));
            __stcg(&g_hT[row * TKN + lane], v);
        }
        gbar();

        // ---- G4: fc2 @ h ----
        gemm_phase(Ws, Xs, lnp, fc2w, g_hT, nullptr, nullptr, nullptr, 0,
                   H_, 256, 32, 16, M_, gidx, group, tid2);
        gbar();

        // ---- C4: s_next = sum + b2 ; output or next-round LN1 stats ----
        {
            if (tid < 64) sm_stat[tid] = 0.f;
            __syncthreads();
            for (int row = gw; row < M_; row += NWARP) {
                float v = psum<32>(M_, row, lane) + fc2b[row];
                if (a == TKA - 1) {
                    out[lane * M_ + row] = v;
                } else {
                    __stcg(&g_sT[row * TKN + lane], v);
                    atomicAdd(&sm_stat[lane], v);
                    atomicAdd(&sm_stat[32 + lane], v * v);
                }
            }
            __syncthreads();
            if (a < TKA - 1 && tid < 64) atomicAdd(&g_ln1s[a + 1][tid], sm_stat[tid]);
        }
        gbar();
    }
}

// ---------------- launch ----------------
extern "C" void kernel_launch(void* const* d_in, const int* in_sizes, int n_in,
                              void* d_out, int out_size) {
    const float* x      = (const float*)d_in[0];
    const float* weight = (const float*)d_in[1];
    // d_in[2] = Wq, d_in[3] = Wk: dead (softmax over size-1 axis == 1)
    const float* Wv     = (const float*)d_in[4];
    const float* Wo     = (const float*)d_in[5];
    const float* ln1g   = (const float*)d_in[6];
    const float* ln1b   = (const float*)d_in[7];
    const float* ln2g   = (const float*)d_in[8];
    const float* ln2b   = (const float*)d_in[9];
    const float* fc1w   = (const float*)d_in[10];
    const float* fc1b   = (const float*)d_in[11];
    const float* fc2w   = (const float*)d_in[12];
    const float* fc2b   = (const float*)d_in[13];
    float* out = (float*)d_out;

    static int smem_set = 0;
    if (!smem_set) {
        cudaFuncSetAttribute(k_main, cudaFuncAttributeMaxDynamicSharedMemorySize, SMEM_BYTES);
        smem_set = 1;
    }
    k_main<<<NBLK, NTHR, SMEM_BYTES>>>(x, weight, Wv, Wo, ln1g, ln1b, ln2g, ln2b,
                                       fc1w, fc1b, fc2w, fc2b, out);
}

// round 12
// speedup vs baseline: 17.0134x; 1.0379x over previous
#include <cuda_runtime.h>
#include <cstdint>

#define NBLK 148
#define NTHR 512
#define NWB  16
#define NWARP (NBLK * NWB)      // 2368
#define GT   128                // threads per GEMM group
#define NG   4                  // groups per block
#define NGRP (NBLK * NG)        // 592
#define M_   2048
#define H_   8192
#define TKN  32
#define TKA  3
#define KC   16                 // K-chunk
#define TILE_R 256
#define WROW 20                 // W smem stride (floats) per row, [row][k] layout
#define XROW 34                 // X smem stride (floats) per k, [k][token] layout
#define WBUF_FLOATS (TILE_R * WROW)     // 5120
#define XBUF_FLOATS (KC * XROW)         // 544
#define GRP_FLOATS (2 * WBUF_FLOATS + 2 * XBUF_FLOATS)  // 11328
#define SMEM_BYTES (NG * GRP_FLOATS * 4)                // 181248

typedef unsigned long long ull;

// ---------------- persistent device state ----------------
__device__ float g_xcfT[M_ * TKN];      // [k][token]
__device__ float g_sT  [M_ * TKN];
__device__ float g_spT [M_ * TKN];
__device__ float g_vcT [M_ * TKN];
__device__ float g_hT  [H_ * TKN];
__device__ float g_part[64 * M_ * TKN]; // K-split partials (16.8 MB)
__device__ float g_ln1s[TKA][64];
__device__ float g_ln2s[TKA][64];
__device__ unsigned g_cnt;
__device__ unsigned g_gen;

// ---------------- grid barrier (sense-reversing) ----------------
__device__ __forceinline__ void gbar() {
    __syncthreads();
    if (threadIdx.x == 0) {
        unsigned my;
        asm volatile("ld.global.relaxed.gpu.u32 %0, [%1];" : "=r"(my) : "l"(&g_gen));
        unsigned old;
        asm volatile("atom.global.add.acq_rel.gpu.u32 %0, [%1], 1;"
                     : "=r"(old) : "l"(&g_cnt));
        if (old == NBLK - 1) {
            unsigned z = 0;
            asm volatile("st.global.relaxed.gpu.u32 [%0], %1;" :: "l"(&g_cnt), "r"(z));
            asm volatile("red.global.add.release.gpu.u32 [%0], %1;" :: "l"(&g_gen), "r"(1u));
        } else {
            unsigned cur;
            do {
                asm volatile("ld.global.acquire.gpu.u32 %0, [%1];" : "=r"(cur) : "l"(&g_gen));
                if (cur == my) __nanosleep(32);
            } while (cur == my);
        }
    }
    __syncthreads();
}
__device__ __forceinline__ void gsync(int group) {
    asm volatile("bar.sync %0, %1;" :: "r"(group + 1), "r"(GT) : "memory");
}

// packed fp32x2 helpers
__device__ __forceinline__ void ffma2(ull& d, ull a, ull b) {
    asm("fma.rn.f32x2 %0, %1, %2, %0;" : "+l"(d) : "l"(a), "l"(b));
}
__device__ __forceinline__ ull dup2(float x) {
    ull r; unsigned xb = __float_as_uint(x);
    asm("mov.b64 %0, {%1, %1};" : "=l"(r) : "r"(xb));
    return r;
}
__device__ __forceinline__ float2 unpk(ull v) {
    unsigned lo, hi;
    asm("mov.b64 {%0, %1}, %2;" : "=r"(lo), "=r"(hi) : "l"(v));
    return make_float2(__uint_as_float(lo), __uint_as_float(hi));
}
__device__ __forceinline__ void cpa16(uint32_t dst, const void* src) {
    asm volatile("cp.async.cg.shared.global [%0], [%1], 16;" :: "r"(dst), "l"(src));
}

// ---------------- GEMM phase: cp.async W + register-blocked 8x8 ------------
// mode: 0 raw, 1 LN1(x), 2 LN2(x)+x.
// Tile 256 rows x 32 tokens; thread (rp=tid2>>2, tp=tid2&3): rows rp+32j, tokens tp*8..+7.
__device__ __forceinline__ void gemm_phase(
    float* grp, uint32_t grp_s, float* lnp,
    const float* __restrict__ W, const float* __restrict__ Xg,
    const float* __restrict__ lng, const float* __restrict__ lnb,
    const float* __restrict__ stat, int mode,
    int Kfull, int KS, int ksplit, int ntiles, int rowstot,
    int gidx, int group, int tid2)
{
    if (mode != 0) {
        if (threadIdx.x < 32) {
            float s = __ldcg(&stat[threadIdx.x]), q = __ldcg(&stat[32 + threadIdx.x]);
            float mu = s * (1.0f / M_);
            float var = fmaxf(q * (1.0f / M_) - mu * mu, 0.f);
            lnp[threadIdx.x] = mu;
            lnp[32 + threadIdx.x] = rsqrtf(var + 1e-5f);
        }
        __syncthreads();
    }
    const int rp = tid2 >> 2, tp = tid2 & 3;
    const int xs_k = tid2 >> 3, xs_t = (tid2 & 7) * 4;
    const int ntasks = ntiles * ksplit;
    const int nchunk = KS / KC;

    for (int task = gidx; task < ntasks; task += NGRP) {
        int rt = task / ksplit, ks = task - rt * ksplit;
        int r0 = rt * TILE_R, k0 = ks * KS;
        ull acc[8][4];
#pragma unroll
        for (int j = 0; j < 8; j++)
#pragma unroll
            for (int p = 0; p < 4; p++) acc[j][p] = 0;

        // prologue: cp.async chunk 0 -> Wbuf0 ; LDG X0 -> regs
#pragma unroll
        for (int i = 0; i < 8; i++) {
            int seg = tid2 + GT * i;            // 0..1023 = 256 rows x 4 k-quads
            int row = seg >> 2, kq = seg & 3;
            cpa16(grp_s + (uint32_t)(row * WROW + kq * 4) * 4,
                  W + (size_t)(r0 + row) * Kfull + k0 + kq * 4);
        }
        asm volatile("cp.async.commit_group;" ::: "memory");
        float4 xr = __ldcg((const float4*)(Xg + (size_t)(k0 + xs_k) * TKN + xs_t));

        for (int c = 0; c < nchunk; c++) {
            int buf = c & 1;
            float* Xsb = grp + 2 * WBUF_FLOATS + buf * XBUF_FLOATS;
            // stage X (fused LN transform) from regs
            {
                float4 xv = xr;
                if (mode != 0) {
                    float gk = __ldg(&lng[k0 + c * KC + xs_k]);
                    float bk = __ldg(&lnb[k0 + c * KC + xs_k]);
                    float n0 = (xv.x - lnp[xs_t + 0]) * lnp[32 + xs_t + 0] * gk + bk;
                    float n1 = (xv.y - lnp[xs_t + 1]) * lnp[32 + xs_t + 1] * gk + bk;
                    float n2 = (xv.z - lnp[xs_t + 2]) * lnp[32 + xs_t + 2] * gk + bk;
                    float n3 = (xv.w - lnp[xs_t + 3]) * lnp[32 + xs_t + 3] * gk + bk;
                    if (mode == 2) { n0 += xv.x; n1 += xv.y; n2 += xv.z; n3 += xv.w; }
                    xv = make_float4(n0, n1, n2, n3);
                }
                float* xd = Xsb + xs_k * XROW + xs_t;
                *(float2*)(xd + 0) = make_float2(xv.x, xv.y);
                *(float2*)(xd + 2) = make_float2(xv.z, xv.w);
            }
            // pipeline next chunk
            if (c + 1 < nchunk) {
                uint32_t wdst = grp_s + (uint32_t)((buf ^ 1) * WBUF_FLOATS) * 4;
#pragma unroll
                for (int i = 0; i < 8; i++) {
                    int seg = tid2 + GT * i;
                    int row = seg >> 2, kq = seg & 3;
                    cpa16(wdst + (uint32_t)(row * WROW + kq * 4) * 4,
                          W + (size_t)(r0 + row) * Kfull + k0 + (c + 1) * KC + kq * 4);
                }
                asm volatile("cp.async.commit_group;" ::: "memory");
                xr = __ldcg((const float4*)(Xg + (size_t)(k0 + (c + 1) * KC + xs_k) * TKN + xs_t));
                asm volatile("cp.async.wait_group 1;" ::: "memory");
            } else {
                asm volatile("cp.async.wait_group 0;" ::: "memory");
            }
            gsync(group);
            // compute: per kk: 8 LDS.32 (W) + 4 LDS.64 (X pairs) + 8 dup + 32 FFMA2
            const float* Wsb = grp + buf * WBUF_FLOATS + rp * WROW;
            const float* xb = Xsb + tp * 8;
#pragma unroll
            for (int kk = 0; kk < KC; kk++) {
                ull x0 = *(const ull*)(xb + kk * XROW + 0);
                ull x1 = *(const ull*)(xb + kk * XROW + 2);
                ull x2 = *(const ull*)(xb + kk * XROW + 4);
                ull x3 = *(const ull*)(xb + kk * XROW + 6);
#pragma unroll
                for (int j = 0; j < 8; j++) {
                    ull wd = dup2(Wsb[j * 32 * WROW + kk]);
                    ffma2(acc[j][0], wd, x0);
                    ffma2(acc[j][1], wd, x1);
                    ffma2(acc[j][2], wd, x2);
                    ffma2(acc[j][3], wd, x3);
                }
            }
            gsync(group);
        }
        // write partials: row = r0 + rp + 32j, tokens tp*8 + 2p, 2p+1
#pragma unroll
        for (int j = 0; j < 8; j++) {
            float* pp = g_part + ((size_t)ks * rowstot + r0 + rp + 32 * j) * TKN + tp * 8;
#pragma unroll
            for (int p = 0; p < 4; p++) {
                float2 v = unpk(acc[j][p]);
                __stcg((float2*)(pp + 2 * p), v);
            }
        }
    }
}

// combine helper
template <int NS>
__device__ __forceinline__ float psum(int rowstot, int row, int lane) {
    float v = 0.f;
#pragma unroll
    for (int ksl = 0; ksl < NS; ksl++)
        v += __ldcg(&g_part[((size_t)ksl * rowstot + row) * TKN + lane]);
    return v;
}

// ---------------- single persistent kernel ----------------
__global__ void __launch_bounds__(NTHR, 1) k_main(
    const float* __restrict__ x,
    const float* __restrict__ weight,
    const float* __restrict__ Wv,   const float* __restrict__ Wo,
    const float* __restrict__ ln1g, const float* __restrict__ ln1b,
    const float* __restrict__ ln2g, const float* __restrict__ ln2b,
    const float* __restrict__ fc1w, const float* __restrict__ fc1b,
    const float* __restrict__ fc2w, const float* __restrict__ fc2b,
    float* __restrict__ out)
{
    extern __shared__ float dsm[];
    __shared__ float lnp[64];
    __shared__ float sm_stat[64];
    const int tid = threadIdx.x, lane = tid & 31, wid = tid >> 5;
    const int bid = blockIdx.x;
    const int group = tid >> 7, tid2 = tid & (GT - 1);
    const int gidx = bid * NG + group;
    const int gw = bid * NWB + wid;
    float* grp = dsm + group * GRP_FLOATS;
    uint32_t grp_s = (uint32_t)__cvta_generic_to_shared(grp);

    // ---- P0: prologue — xcf + zero LN stats ----
    {
        int idx = bid * NTHR + tid;
        if (idx < TKN * M_) {
            int i = idx >> 11, m = idx & 2047;
            int b = m >> 4, ab = m & 15;
            const float* p = x + ab * (128 * 512) + b * 512 + i * 16;
            float s = 0.f;
#pragma unroll
            for (int t = 0; t < 16; t++) s += p[t];
            __stcg(&g_xcfT[m * TKN + i], s * (1.0f / 16.0f));
        }
        if (bid == 0 && tid < TKA * 64) {
            __stcg(&((float*)g_ln1s)[tid], 0.f);
            __stcg(&((float*)g_ln2s)[tid], 0.f);
        }
    }
    gbar();

    // ---- s0 GEMM: tiles 8, ksplit 64 (KS=32, 2 chunks) ----
    gemm_phase(grp, grp_s, lnp, weight, g_xcfT, nullptr, nullptr, nullptr, 0,
               M_, 32, 64, 8, M_, gidx, group, tid2);
    gbar();

    // ---- C_s0 ----
    {
        if (tid < 64) sm_stat[tid] = 0.f;
        __syncthreads();
        for (int row = gw; row < M_; row += NWARP) {
            float v = psum<64>(M_, row, lane);
            int p = row >> 1;
            float ang = (float)lane * expf(-(float)p * (9.210340371976184f / 512.0f));
            v += (row & 1) ? cosf(ang) : sinf(ang);
            __stcg(&g_sT[row * TKN + lane], v);
            atomicAdd(&sm_stat[lane], v);
            atomicAdd(&sm_stat[32 + lane], v * v);
        }
        __syncthreads();
        if (tid < 64) atomicAdd(&((float*)g_ln1s)[tid], sm_stat[tid]);
    }
    gbar();

    for (int a = 0; a < TKA; a++) {
        // ---- G1: v = Wv[a] @ LN1(s) ----
        gemm_phase(grp, grp_s, lnp, Wv + (size_t)a * M_ * M_, g_sT, ln1g, ln1b,
                   g_ln1s[a], 1, M_, 32, 64, 8, M_, gidx, group, tid2);
        gbar();

        // ---- C1: vcum prefix-sum over tokens ----
        for (int row = gw; row < M_; row += NWARP) {
            float v = psum<64>(M_, row, lane);
#pragma unroll
            for (int o = 1; o < 32; o <<= 1) {
                float n = __shfl_up_sync(0xffffffffu, v, o);
                if (lane >= o) v += n;
            }
            __stcg(&g_vcT[row * TKN + lane], v);
        }
        gbar();

        // ---- G2: Wo[a] @ vcum ----
        gemm_phase(grp, grp_s, lnp, Wo + (size_t)a * M_ * M_, g_vcT, nullptr, nullptr,
                   nullptr, 0, M_, 32, 64, 8, M_, gidx, group, tid2);
        gbar();

        // ---- C2: s' = sum + s ; LN2 stats ----
        {
            if (tid < 64) sm_stat[tid] = 0.f;
            __syncthreads();
            for (int row = gw; row < M_; row += NWARP) {
                float v = psum<64>(M_, row, lane) + __ldcg(&g_sT[row * TKN + lane]);
                __stcg(&g_spT[row * TKN + lane], v);
                atomicAdd(&sm_stat[lane], v);
                atomicAdd(&sm_stat[32 + lane], v * v);
            }
            __syncthreads();
            if (tid < 64) atomicAdd(&g_ln2s[a][tid], sm_stat[tid]);
        }
        gbar();

        // ---- G3: fc1 @ (LN2(s')+s'): tiles 32, ksplit 16 (KS=128, 8 chunks) ----
        gemm_phase(grp, grp_s, lnp, fc1w, g_spT, ln2g, ln2b, g_ln2s[a], 2,
                   M_, 128, 16, 32, H_, gidx, group, tid2);
        gbar();

        // ---- C3: h = gelu(sum + b1) ----
        for (int row = gw; row < H_; row += NWARP) {
            float v = psum<16>(H_, row, lane) + fc1b[row];
            v = 0.5f * v * (1.0f + erff(v * 0.70710678118654752f));
            __stcg(&g_hT[row * TKN + lane], v);
        }
        gbar();

        // ---- G4: fc2 @ h: tiles 8, ksplit 64 (KS=128, 8 chunks) ----
        gemm_phase(grp, grp_s, lnp, fc2w, g_hT, nullptr, nullptr, nullptr, 0,
                   H_, 128, 64, 8, M_, gidx, group, tid2);
        gbar();

        // ---- C4: s_next = sum + b2 ----
        {
            if (tid < 64) sm_stat[tid] = 0.f;
            __syncthreads();
            for (int row = gw; row < M_; row += NWARP) {
                float v = psum<64>(M_, row, lane) + fc2b[row];
                if (a == TKA - 1) {
                    out[lane * M_ + row] = v;
                } else {
                    __stcg(&g_sT[row * TKN + lane], v);
                    atomicAdd(&sm_stat[lane], v);
                    atomicAdd(&sm_stat[32 + lane], v * v);
                }
            }
            __syncthreads();
            if (a < TKA - 1 && tid < 64) atomicAdd(&g_ln1s[a + 1][tid], sm_stat[tid]);
        }
        gbar();
    }
}

// ---------------- launch ----------------
extern "C" void kernel_launch(void* const* d_in, const int* in_sizes, int n_in,
                              void* d_out, int out_size) {
    const float* x      = (const float*)d_in[0];
    const float* weight = (const float*)d_in[1];
    // d_in[2] = Wq, d_in[3] = Wk: dead (softmax over size-1 axis == 1)
    const float* Wv     = (const float*)d_in[4];
    const float* Wo     = (const float*)d_in[5];
    const float* ln1g   = (const float*)d_in[6];
    const float* ln1b   = (const float*)d_in[7];
    const float* ln2g   = (const float*)d_in[8];
    const float* ln2b   = (const float*)d_in[9];
    const float* fc1w   = (const float*)d_in[10];
    const float* fc1b   = (const float*)d_in[11];
    const float* fc2w   = (const float*)d_in[12];
    const float* fc2b   = (const float*)d_in[13];
    float* out = (float*)d_out;

    static int smem_set = 0;
    if (!smem_set) {
        cudaFuncSetAttribute(k_main, cudaFuncAttributeMaxDynamicSharedMemorySize, SMEM_BYTES);
        smem_set = 1;
    }
    k_main<<<NBLK, NTHR, SMEM_BYTES>>>(x, weight, Wv, Wo, ln1g, ln1b, ln2g, ln2b,
                                       fc1w, fc1b, fc2w, fc2b, out);
}